// round 7
// baseline (speedup 1.0000x reference)
#include <cuda_runtime.h>
#include <math.h>

#define NN 32768
#define FF 64
#define HH 4
#define HFD 256
#define ESZ 524288
#define EGZ 524288
#define GG 64
#define NCC 10
#define BNEPS 1e-5f

// ---------------- float scratch arena ----------------------------------------
#define O_B0     0
#define O_BR     (O_B0 + NN*FF)
#define O_X      (O_BR + 3*NN*FF)
#define O_H      (O_X + 3*NN*FF)
#define O_ATT    (O_H + NN*HFD)
#define O_AS     (O_ATT + NN*HFD)
#define O_AD     (O_AS + NN*HH)
#define O_AEX    (O_AD + NN*HH)
#define O_SEXP   (O_AEX + EGZ*HH)
#define O_INV    (O_SEXP + NN*HH)
#define O_C0A    (O_INV + NN*HH)
#define O_Z      (O_C0A + ESZ)
#define O_XACC   (O_Z + NN*FF)
#define O_STATS  (O_XACC + NN*FF)
#define O_POOL   (O_STATS + 512)
#define ARENA_SZ (O_POOL + GG*FF)

__device__ __align__(256) float g_arena[ARENA_SZ];

// ---------------- int scratch arena -------------------------------------------
#define I_DEGE 0
#define I_CURE (I_DEGE + NN)
#define I_RPE  (I_CURE + NN)
#define I_CSRE (I_RPE + NN)
#define I_DEG0 (I_CSRE + EGZ)
#define I_CUR0 (I_DEG0 + NN)
#define I_RP0  (I_CUR0 + NN)
#define I_CSR0 (I_RP0 + NN)
#define I_BSUM (I_CSR0 + ESZ)
#define IARENA_SZ (I_BSUM + 128)

__device__ __align__(256) int g_iarena[IARENA_SZ];

// ---------------- helpers -----------------------------------------------------
__device__ __forceinline__ void red4(float* a, float4 v) {
    asm volatile("red.global.add.v4.f32 [%0], {%1,%2,%3,%4};"
                 :: "l"(a), "f"(v.x), "f"(v.y), "f"(v.z), "f"(v.w) : "memory");
}
__device__ __forceinline__ float lrelu(float v) { return v > 0.f ? v : 0.2f * v; }
__device__ __forceinline__ float eluf(float v)  { return v > 0.f ? v : __expf(v) - 1.f; }

// ---------------- CSR build ---------------------------------------------------
__global__ __launch_bounds__(256) void k_hist(const int* __restrict__ dst, int* __restrict__ deg)
{
    int e = blockIdx.x * 256 + threadIdx.x;
    atomicAdd(&deg[dst[e]], 1);
}

__global__ __launch_bounds__(256) void k_blocksum(
    const int* __restrict__ deg, int* __restrict__ bsum)
{
    __shared__ int sh[256];
    int t = threadIdx.x;
    sh[t] = deg[blockIdx.x * 256 + t];
    __syncthreads();
#pragma unroll
    for (int off = 128; off; off >>= 1) {
        if (t < off) sh[t] += sh[t + off];
        __syncthreads();
    }
    if (t == 0) bsum[blockIdx.x] = sh[0];
}

__global__ __launch_bounds__(128) void k_scanbs(int* __restrict__ bsum)
{
    __shared__ int sh[128];
    int t = threadIdx.x;
    int v = bsum[t];
    sh[t] = v;
    __syncthreads();
#pragma unroll
    for (int off = 1; off < 128; off <<= 1) {
        int u = (t >= off) ? sh[t - off] : 0;
        __syncthreads();
        sh[t] += u;
        __syncthreads();
    }
    bsum[t] = sh[t] - v;
}

__global__ __launch_bounds__(256) void k_scanout(
    const int* __restrict__ deg, const int* __restrict__ bsum,
    int* __restrict__ rowptr, int* __restrict__ cur)
{
    __shared__ int sh[256];
    int t = threadIdx.x;
    int g = blockIdx.x * 256 + t;
    int v = deg[g];
    sh[t] = v;
    __syncthreads();
#pragma unroll
    for (int off = 1; off < 256; off <<= 1) {
        int u = (t >= off) ? sh[t - off] : 0;
        __syncthreads();
        sh[t] += u;
        __syncthreads();
    }
    int ex = sh[t] - v + bsum[blockIdx.x];
    rowptr[g] = ex;
    cur[g] = ex;
}

__global__ __launch_bounds__(256) void k_fillE(
    const int* __restrict__ ei, int* __restrict__ cur, int* __restrict__ csr)
{
    int e = blockIdx.x * 256 + threadIdx.x;
    int d = ei[EGZ + e];
    int p = atomicAdd(&cur[d], 1);
    csr[p] = ei[e];
}

__global__ __launch_bounds__(256) void k_fill0(
    const int* __restrict__ si, const float* __restrict__ sattr,
    int* __restrict__ cur, int* __restrict__ csr, float* __restrict__ csra)
{
    int e = blockIdx.x * 256 + threadIdx.x;
    int d = si[ESZ + e];
    int p = atomicAdd(&cur[d], 1);
    csr[p] = si[e];
    csra[p] = sattr[e];
}

// ---------------- merged atomic scatter (3 passes via grid.y) -----------------
__global__ __launch_bounds__(256) void k_scatter3(
    const int* __restrict__ sidx, const float* __restrict__ sattr,
    const float* __restrict__ xin, float* __restrict__ brout)
{
    int j = blockIdx.y + 1;
    const int* src  = sidx + j * 2 * ESZ;
    const int* dst  = src + ESZ;
    const float* at = sattr + j * ESZ;
    float* outb = brout + (size_t)(j - 1) * NN * FF;

    int t = blockIdx.x * 256 + threadIdx.x;
    int e = t >> 4, lane = t & 15;
    int s = src[e], d = dst[e];
    float a = at[e];
    float4 v = ((const float4*)xin)[s * 16 + lane];
    v.x *= a; v.y *= a; v.z *= a; v.w *= a;
    red4(outb + d * 64 + lane * 4, v);
}

// ---------------- merged CSR gathers (4 via grid.y), pipelined ---------------
__global__ __launch_bounds__(256) void k_gather4(
    const int* __restrict__ rowptr, const int* __restrict__ deg,
    const int* __restrict__ csr, const float* __restrict__ csra,
    const float* __restrict__ x, const float* __restrict__ brin,
    float* __restrict__ b0out, float* __restrict__ xout)
{
    int br = blockIdx.y;
    const float* xin = (br == 0) ? x : brin + (size_t)(br - 1) * NN * FF;
    float* outb = (br == 0) ? b0out : xout + (size_t)(br - 1) * NN * FF;
    int doAbs = (br > 0);

    int t = blockIdx.x * 256 + threadIdx.x;
    int n = t >> 4, q = t & 15;
    int b = rowptr[n], dg = deg[n];
    float4 acc = make_float4(0.f, 0.f, 0.f, 0.f);
    const float4* xin4 = (const float4*)xin;
    if (dg > 0) {
        int s = csr[b];
        float a = csra[b];
        for (int p = b; p < b + dg - 1; p++) {
            float4 v = xin4[s * 16 + q];
            int s2 = csr[p + 1];
            float a2 = csra[p + 1];
            if (doAbs) { v.x = fabsf(v.x); v.y = fabsf(v.y); v.z = fabsf(v.z); v.w = fabsf(v.w); }
            acc.x += a * v.x; acc.y += a * v.y; acc.z += a * v.z; acc.w += a * v.w;
            s = s2; a = a2;
        }
        float4 v = xin4[s * 16 + q];
        if (doAbs) { v.x = fabsf(v.x); v.y = fabsf(v.y); v.z = fabsf(v.z); v.w = fabsf(v.w); }
        acc.x += a * v.x; acc.y += a * v.y; acc.z += a * v.z; acc.w += a * v.w;
    }
    ((float4*)outb)[n * 16 + q] = acc;
}

// ---------------- GEMM1 (64 rows/block) + fused attcoef -----------------------
__global__ __launch_bounds__(256) void k_gemm_h(
    const float* __restrict__ xin, const float* __restrict__ W,
    const float* __restrict__ asrc, const float* __restrict__ adst,
    float* __restrict__ h, float* __restrict__ as_, float* __restrict__ ad_)
{
    __shared__ float xs[64 * 65];
    int t = threadIdx.x;
    int row0 = blockIdx.x * 64;
    for (int i = t; i < 64 * 16; i += 256) {
        int r = i >> 4, c4 = i & 15;
        float4 v = ((const float4*)(xin + (size_t)(row0 + r) * 64))[c4];
        float* dp = &xs[r * 65 + c4 * 4];
        dp[0] = v.x; dp[1] = v.y; dp[2] = v.z; dp[3] = v.w;
    }
    __syncthreads();
    int tx = t & 63, ty = t >> 6;
    float4 acc[16];
#pragma unroll
    for (int r = 0; r < 16; r++) acc[r] = make_float4(0.f, 0.f, 0.f, 0.f);
    const float4* W4 = (const float4*)W;
#pragma unroll 4
    for (int k = 0; k < 64; k++) {
        float4 w = W4[k * 64 + tx];
#pragma unroll
        for (int r = 0; r < 16; r++) {
            float xv = xs[(ty * 16 + r) * 65 + k];
            acc[r].x += xv * w.x; acc[r].y += xv * w.y;
            acc[r].z += xv * w.z; acc[r].w += xv * w.w;
        }
    }
#pragma unroll
    for (int r = 0; r < 16; r++)
        ((float4*)h)[(size_t)(row0 + ty * 16 + r) * 64 + tx] = acc[r];
    float4 asv = ((const float4*)asrc)[tx];
    float4 adv = ((const float4*)adst)[tx];
    int hd = tx >> 4;
#pragma unroll
    for (int r = 0; r < 16; r++) {
        float ps = acc[r].x * asv.x + acc[r].y * asv.y + acc[r].z * asv.z + acc[r].w * asv.w;
        float pd = acc[r].x * adv.x + acc[r].y * adv.y + acc[r].z * adv.z + acc[r].w * adv.w;
#pragma unroll
        for (int o = 8; o; o >>= 1) {
            ps += __shfl_xor_sync(0xffffffffu, ps, o);
            pd += __shfl_xor_sync(0xffffffffu, pd, o);
        }
        if ((tx & 15) == 0) {
            int row = row0 + ty * 16 + r;
            as_[row * 4 + hd] = ps;
            ad_[row * 4 + hd] = pd;
        }
    }
}

// ---------------- per-node softmax over CSR (warp/node) -----------------------
__global__ __launch_bounds__(256) void k_softmax(
    const int* __restrict__ rowptr, const int* __restrict__ deg, const int* __restrict__ csr,
    const float* __restrict__ as_, const float* __restrict__ ad_,
    float* __restrict__ aex, float* __restrict__ sexp, float* __restrict__ inv)
{
    int n = blockIdx.x * 8 + (threadIdx.x >> 5);
    int lane = threadIdx.x & 31;
    int b = rowptr[n], dg = deg[n];
    float4 adn = ((const float4*)ad_)[n];
    float4 asn = ((const float4*)as_)[n];
    float4 self;
    self.x = lrelu(asn.x + adn.x); self.y = lrelu(asn.y + adn.y);
    self.z = lrelu(asn.z + adn.z); self.w = lrelu(asn.w + adn.w);

    float4 mx = self;
    for (int j = lane; j < dg; j += 32) {
        float4 sv = ((const float4*)as_)[csr[b + j]];
        mx.x = fmaxf(mx.x, lrelu(sv.x + adn.x));
        mx.y = fmaxf(mx.y, lrelu(sv.y + adn.y));
        mx.z = fmaxf(mx.z, lrelu(sv.z + adn.z));
        mx.w = fmaxf(mx.w, lrelu(sv.w + adn.w));
    }
#pragma unroll
    for (int o = 16; o; o >>= 1) {
        mx.x = fmaxf(mx.x, __shfl_xor_sync(0xffffffffu, mx.x, o));
        mx.y = fmaxf(mx.y, __shfl_xor_sync(0xffffffffu, mx.y, o));
        mx.z = fmaxf(mx.z, __shfl_xor_sync(0xffffffffu, mx.z, o));
        mx.w = fmaxf(mx.w, __shfl_xor_sync(0xffffffffu, mx.w, o));
    }

    float4 sum = make_float4(0.f, 0.f, 0.f, 0.f);
    for (int j = lane; j < dg; j += 32) {
        float4 sv = ((const float4*)as_)[csr[b + j]];
        float4 ex;
        ex.x = __expf(lrelu(sv.x + adn.x) - mx.x);
        ex.y = __expf(lrelu(sv.y + adn.y) - mx.y);
        ex.z = __expf(lrelu(sv.z + adn.z) - mx.z);
        ex.w = __expf(lrelu(sv.w + adn.w) - mx.w);
        ((float4*)aex)[b + j] = ex;
        sum.x += ex.x; sum.y += ex.y; sum.z += ex.z; sum.w += ex.w;
    }
#pragma unroll
    for (int o = 16; o; o >>= 1) {
        sum.x += __shfl_xor_sync(0xffffffffu, sum.x, o);
        sum.y += __shfl_xor_sync(0xffffffffu, sum.y, o);
        sum.z += __shfl_xor_sync(0xffffffffu, sum.z, o);
        sum.w += __shfl_xor_sync(0xffffffffu, sum.w, o);
    }
    if (lane == 0) {
        float4 sex;
        sex.x = __expf(self.x - mx.x); sex.y = __expf(self.y - mx.y);
        sex.z = __expf(self.z - mx.z); sex.w = __expf(self.w - mx.w);
        float4 iv;
        iv.x = 1.f / (sum.x + sex.x); iv.y = 1.f / (sum.y + sex.y);
        iv.z = 1.f / (sum.z + sex.z); iv.w = 1.f / (sum.w + sex.w);
        ((float4*)sexp)[n] = sex;
        ((float4*)inv)[n] = iv;
    }
}

// ---------------- CSR gather aggregation (pipelined) --------------------------
__global__ __launch_bounds__(256) void k_aggr(
    const int* __restrict__ rowptr, const int* __restrict__ deg, const int* __restrict__ csr,
    const float* __restrict__ aex, const float* __restrict__ sexp, const float* __restrict__ inv,
    const float* __restrict__ h, float* __restrict__ att)
{
    int t = blockIdx.x * 256 + threadIdx.x;
    int n = t >> 6, gq = t & 63, hd = gq >> 4;
    int b = rowptr[n], dg = deg[n];
    float sex = sexp[n * 4 + hd];
    float iv  = inv[n * 4 + hd];
    const float4* h4 = (const float4*)h;
    float4 acc = h4[(size_t)n * 64 + gq];
    acc.x *= sex; acc.y *= sex; acc.z *= sex; acc.w *= sex;
    if (dg > 0) {
        int s = csr[b];
        float al = aex[b * 4 + hd];
        for (int p = b; p < b + dg - 1; p++) {
            float4 hv = h4[(size_t)s * 64 + gq];
            int s2 = csr[p + 1];
            float al2 = aex[(p + 1) * 4 + hd];
            acc.x += al * hv.x; acc.y += al * hv.y;
            acc.z += al * hv.z; acc.w += al * hv.w;
            s = s2; al = al2;
        }
        float4 hv = h4[(size_t)s * 64 + gq];
        acc.x += al * hv.x; acc.y += al * hv.y;
        acc.z += al * hv.z; acc.w += al * hv.w;
    }
    acc.x *= iv; acc.y *= iv; acc.z *= iv; acc.w *= iv;
    ((float4*)att)[(size_t)n * 64 + gq] = acc;
}

// ---------------- GEMM2 + fused BN stats --------------------------------------
__global__ __launch_bounds__(256) void k_gemm_z(
    const float* __restrict__ att, const float* __restrict__ bias,
    const float* __restrict__ W, float* __restrict__ z, float* __restrict__ stats)
{
    __shared__ float As[64 * 65];
    __shared__ float red[16][64];
    int t = threadIdx.x;
    int row0 = blockIdx.x * 64;
    int tx = t & 15, ty = t >> 4;
    float4 acc[4];
    acc[0] = acc[1] = acc[2] = acc[3] = make_float4(0.f, 0.f, 0.f, 0.f);
    const float4* W4 = (const float4*)W;
    for (int kc = 0; kc < 4; kc++) {
        __syncthreads();
        for (int i = t; i < 1024; i += 256) {
            int r = i >> 4, c4 = i & 15;
            float4 v = ((const float4*)(att + (size_t)(row0 + r) * 256 + kc * 64))[c4];
            float4 b = ((const float4*)(bias + kc * 64))[c4];
            float* dp = &As[r * 65 + c4 * 4];
            dp[0] = eluf(v.x + b.x); dp[1] = eluf(v.y + b.y);
            dp[2] = eluf(v.z + b.z); dp[3] = eluf(v.w + b.w);
        }
        __syncthreads();
#pragma unroll 8
        for (int k = 0; k < 64; k++) {
            float4 w = W4[(kc * 64 + k) * 16 + tx];
#pragma unroll
            for (int ri = 0; ri < 4; ri++) {
                float av = As[(ty * 4 + ri) * 65 + k];
                acc[ri].x += av * w.x; acc[ri].y += av * w.y;
                acc[ri].z += av * w.z; acc[ri].w += av * w.w;
            }
        }
    }
#pragma unroll
    for (int ri = 0; ri < 4; ri++)
        ((float4*)z)[(size_t)(row0 + ty * 4 + ri) * 16 + tx] = acc[ri];

    float cs[4];
    cs[0] = acc[0].x + acc[1].x + acc[2].x + acc[3].x;
    cs[1] = acc[0].y + acc[1].y + acc[2].y + acc[3].y;
    cs[2] = acc[0].z + acc[1].z + acc[2].z + acc[3].z;
    cs[3] = acc[0].w + acc[1].w + acc[2].w + acc[3].w;
    __syncthreads();
#pragma unroll
    for (int c = 0; c < 4; c++) red[ty][tx * 4 + c] = cs[c];
    __syncthreads();
    if (t < 64) {
        float s = 0.f;
#pragma unroll
        for (int r = 0; r < 16; r++) s += red[r][t];
        atomicAdd(&stats[t], s);
    }
    cs[0] = acc[0].x*acc[0].x + acc[1].x*acc[1].x + acc[2].x*acc[2].x + acc[3].x*acc[3].x;
    cs[1] = acc[0].y*acc[0].y + acc[1].y*acc[1].y + acc[2].y*acc[2].y + acc[3].y*acc[3].y;
    cs[2] = acc[0].z*acc[0].z + acc[1].z*acc[1].z + acc[2].z*acc[2].z + acc[3].z*acc[3].z;
    cs[3] = acc[0].w*acc[0].w + acc[1].w*acc[1].w + acc[2].w*acc[2].w + acc[3].w*acc[3].w;
    __syncthreads();
#pragma unroll
    for (int c = 0; c < 4; c++) red[ty][tx * 4 + c] = cs[c];
    __syncthreads();
    if (t < 64) {
        float s = 0.f;
#pragma unroll
        for (int r = 0; r < 16; r++) s += red[r][t];
        atomicAdd(&stats[FF + t], s);
    }
}

// ---------------- BN apply (fused finstats; init / accumulate / pool) ---------
__global__ __launch_bounds__(256) void k_bnapply(
    const float* __restrict__ z, const float* __restrict__ stats,
    const float* __restrict__ g, const float* __restrict__ be,
    const float* __restrict__ base, const int* __restrict__ batch,
    float* __restrict__ xacc, float* __restrict__ pool, int doPool)
{
    __shared__ float sm_mu[64], sm_rs[64], sm_b[64];
    int t = threadIdx.x;
    if (t < 64) {
        float mu = stats[t] * (1.f / NN);
        float var = stats[FF + t] * (1.f / NN) - mu * mu;
        sm_mu[t] = mu;
        sm_rs[t] = rsqrtf(var + BNEPS) * g[t];
        sm_b[t] = be[t];
    }
    __syncthreads();
    int gidx = blockIdx.x * 256 + t;
    int n = gidx >> 4, q = gidx & 15, f0 = q * 4;
    float4 zv = ((const float4*)z)[gidx];
    float4 v;
    v.x = (zv.x - sm_mu[f0 + 0]) * sm_rs[f0 + 0] + sm_b[f0 + 0];
    v.y = (zv.y - sm_mu[f0 + 1]) * sm_rs[f0 + 1] + sm_b[f0 + 1];
    v.z = (zv.z - sm_mu[f0 + 2]) * sm_rs[f0 + 2] + sm_b[f0 + 2];
    v.w = (zv.w - sm_mu[f0 + 3]) * sm_rs[f0 + 3] + sm_b[f0 + 3];
    float4 bv;
    if (base) bv = ((const float4*)base)[gidx];
    else      bv = ((const float4*)xacc)[gidx];
    v.x += bv.x; v.y += bv.y; v.z += bv.z; v.w += bv.w;
    ((float4*)xacc)[gidx] = v;
    if (doPool) red4(pool + batch[n] * 64 + f0, v);
}

// ---------------- fused FC head (single block, 1024 threads) ------------------
__global__ __launch_bounds__(1024) void k_head(
    const float* __restrict__ pool,
    const float* __restrict__ fc1W, const float* __restrict__ fc1b,
    const float* __restrict__ fc1g, const float* __restrict__ fc1be,
    const float* __restrict__ fc2W, const float* __restrict__ fc2b,
    const float* __restrict__ fc2g, const float* __restrict__ fc2be,
    const float* __restrict__ fc3W, const float* __restrict__ fc3b,
    const float* __restrict__ fc3g, const float* __restrict__ fc3be,
    float* __restrict__ out)
{
    extern __shared__ float sm[];
    float* sp = sm;
    float* y1 = sp + 64 * 65;
    float* y2 = y1 + 64 * 257;
    int t = threadIdx.x;

    for (int i = t; i < 64 * 16; i += 1024) {
        int r = i >> 4, c4 = i & 15;
        float4 v = ((const float4*)pool)[i];
        float* dp = &sp[r * 65 + c4 * 4];
        dp[0] = v.x; dp[1] = v.y; dp[2] = v.z; dp[3] = v.w;
    }
    __syncthreads();

    {
        int c = t & 255, rg = t >> 8;
        float accv[16];
        float bb = fc1b[c];
#pragma unroll
        for (int r = 0; r < 16; r++) accv[r] = bb;
        for (int k = 0; k < 64; k++) {
            float w = fc1W[k * 256 + c];
#pragma unroll
            for (int r = 0; r < 16; r++)
                accv[r] += sp[(rg * 16 + r) * 65 + k] * w;
        }
#pragma unroll
        for (int r = 0; r < 16; r++) y1[(rg * 16 + r) * 257 + c] = accv[r];
    }
    __syncthreads();
    if (t < 256) {
        float s = 0.f, ss = 0.f;
#pragma unroll 8
        for (int r = 0; r < 64; r++) { float v = y1[r * 257 + t]; s += v; ss += v * v; }
        float mu = s * (1.f / GG);
        float var = ss * (1.f / GG) - mu * mu;
        sp[t] = mu;
        sp[256 + t] = rsqrtf(var + BNEPS) * fc1g[t];
    }
    __syncthreads();
    for (int i = t; i < 64 * 256; i += 1024) {
        int r = i >> 8, c = i & 255;
        float v = (y1[r * 257 + c] - sp[c]) * sp[256 + c] + fc1be[c];
        y1[r * 257 + c] = fmaxf(v, 0.f);
    }
    __syncthreads();

    {
        int c = t & 127, rg = t >> 7;
        float accv[8];
        float bb = fc2b[c];
#pragma unroll
        for (int r = 0; r < 8; r++) accv[r] = bb;
        for (int k = 0; k < 256; k++) {
            float w = fc2W[k * 128 + c];
#pragma unroll
            for (int r = 0; r < 8; r++)
                accv[r] += y1[(rg * 8 + r) * 257 + k] * w;
        }
#pragma unroll
        for (int r = 0; r < 8; r++) y2[(rg * 8 + r) * 129 + c] = accv[r];
    }
    __syncthreads();
    if (t < 128) {
        float s = 0.f, ss = 0.f;
#pragma unroll 8
        for (int r = 0; r < 64; r++) { float v = y2[r * 129 + t]; s += v; ss += v * v; }
        float mu = s * (1.f / GG);
        float var = ss * (1.f / GG) - mu * mu;
        sp[t] = mu;
        sp[256 + t] = rsqrtf(var + BNEPS) * fc2g[t];
    }
    __syncthreads();
    for (int i = t; i < 64 * 128; i += 1024) {
        int r = i >> 7, c = i & 127;
        float v = (y2[r * 129 + c] - sp[c]) * sp[256 + c] + fc2be[c];
        y2[r * 129 + c] = fmaxf(v, 0.f);
    }
    __syncthreads();

    float* y3 = sp + 1024;
    if (t < 640) {
        int r = t / NCC, c = t % NCC;
        float acc = fc3b[c];
        for (int k = 0; k < 128; k++)
            acc += y2[r * 129 + k] * fc3W[k * NCC + c];
        y3[r * NCC + c] = acc;
    }
    __syncthreads();
    if (t < NCC) {
        float s = 0.f, ss = 0.f;
#pragma unroll 8
        for (int r = 0; r < 64; r++) { float v = y3[r * NCC + t]; s += v; ss += v * v; }
        float mu = s * (1.f / GG);
        float var = ss * (1.f / GG) - mu * mu;
        sp[t] = mu;
        sp[64 + t] = rsqrtf(var + BNEPS) * fc3g[t];
    }
    __syncthreads();
    if (t < 640) {
        int r = t / NCC, c = t % NCC;
        out[t] = (y3[r * NCC + c] - sp[c]) * sp[64 + c] + fc3be[c];
    }
}

// ---------------- host orchestration ------------------------------------------
extern "C" void kernel_launch(void* const* d_in, const int* in_sizes, int n_in,
                              void* d_out, int out_size)
{
    const float* x      = (const float*)d_in[0];
    const int*   eidx   = (const int*)d_in[1];
    const int*   batch  = (const int*)d_in[2];
    const int*   sidx   = (const int*)d_in[3];
    const float* sattr  = (const float*)d_in[4];
    const float* gatW   = (const float*)d_in[5];
    const float* gasrc  = (const float*)d_in[6];
    const float* gadst  = (const float*)d_in[7];
    const float* gatb   = (const float*)d_in[8];
    const float* mlpW   = (const float*)d_in[9];
    const float* mlpg   = (const float*)d_in[11];
    const float* mlpbe  = (const float*)d_in[12];
    const float* fc1W   = (const float*)d_in[13];
    const float* fc1b   = (const float*)d_in[14];
    const float* fc1g   = (const float*)d_in[15];
    const float* fc1be  = (const float*)d_in[16];
    const float* fc2W   = (const float*)d_in[17];
    const float* fc2b   = (const float*)d_in[18];
    const float* fc2g   = (const float*)d_in[19];
    const float* fc2be  = (const float*)d_in[20];
    const float* fc3W   = (const float*)d_in[21];
    const float* fc3b   = (const float*)d_in[22];
    const float* fc3g   = (const float*)d_in[23];
    const float* fc3be  = (const float*)d_in[24];
    float* out = (float*)d_out;

    float* A;
    cudaGetSymbolAddress((void**)&A, g_arena);
    int* IA;
    cudaGetSymbolAddress((void**)&IA, g_iarena);

    float* B0   = A + O_B0;
    float* BR   = A + O_BR;
    float* X123 = A + O_X;
    float* H    = A + O_H;
    float* ATT  = A + O_ATT;
    float* AS   = A + O_AS;
    float* AD   = A + O_AD;
    float* AEX  = A + O_AEX;
    float* SEXP = A + O_SEXP;
    float* INV  = A + O_INV;
    float* C0A  = A + O_C0A;
    float* Z    = A + O_Z;
    float* XACC = A + O_XACC;
    float* ST   = A + O_STATS;
    float* POOL = A + O_POOL;

    int* DEGE = IA + I_DEGE;
    int* CURE = IA + I_CURE;
    int* RPE  = IA + I_RPE;
    int* CSRE = IA + I_CSRE;
    int* DEG0 = IA + I_DEG0;
    int* CUR0 = IA + I_CUR0;
    int* RP0  = IA + I_RP0;
    int* CSR0 = IA + I_CSR0;
    int* BSUM = IA + I_BSUM;

    static int head_configured = 0;
    if (!head_configured) {
        cudaFuncSetAttribute(k_head, cudaFuncAttributeMaxDynamicSharedMemorySize, 120 * 1024);
        head_configured = 1;
    }

    // ---- CSR builds ----
    cudaMemsetAsync(DEGE, 0, NN * sizeof(int));
    cudaMemsetAsync(DEG0, 0, NN * sizeof(int));
    cudaMemsetAsync(ST, 0, 512 * sizeof(float));
    cudaMemsetAsync(POOL, 0, (size_t)GG * FF * sizeof(float));
    cudaMemsetAsync(BR, 0, (size_t)3 * NN * FF * sizeof(float));
    k_hist<<<EGZ / 256, 256>>>(eidx + EGZ, DEGE);
    k_hist<<<ESZ / 256, 256>>>(sidx + ESZ, DEG0);
    k_blocksum<<<NN / 256, 256>>>(DEGE, BSUM);
    k_scanbs<<<1, 128>>>(BSUM);
    k_scanout<<<NN / 256, 256>>>(DEGE, BSUM, RPE, CURE);
    k_fillE<<<EGZ / 256, 256>>>(eidx, CURE, CSRE);
    k_blocksum<<<NN / 256, 256>>>(DEG0, BSUM);
    k_scanbs<<<1, 128>>>(BSUM);
    k_scanout<<<NN / 256, 256>>>(DEG0, BSUM, RP0, CUR0);
    k_fill0<<<ESZ / 256, 256>>>(sidx, sattr, CUR0, CSR0, C0A);

    // ---- scatter stage (merged) ----
    dim3 sg(ESZ * 16 / 256, 3);
    k_scatter3<<<sg, 256>>>(sidx, sattr, x, BR);
    dim3 gg(NN * 16 / 256, 4);
    k_gather4<<<gg, 256>>>(RP0, DEG0, CSR0, C0A, x, BR, B0, X123);

    const float* bx[4] = { B0, X123, X123 + NN * FF, X123 + 2 * NN * FF };

    // ---- 4 GAT branches ----
    for (int br = 0; br < 4; br++) {
        k_gemm_h<<<NN / 64, 256>>>(bx[br], gatW + br * FF * HFD,
                                   gasrc + br * HH * FF, gadst + br * HH * FF,
                                   H, AS, AD);
        k_softmax<<<NN / 8, 256>>>(RPE, DEGE, CSRE, AS, AD, AEX, SEXP, INV);
        k_aggr<<<NN * 64 / 256, 256>>>(RPE, DEGE, CSRE, AEX, SEXP, INV, H, ATT);
        k_gemm_z<<<NN / 64, 256>>>(ATT, gatb + br * HFD, mlpW + br * HFD * FF, Z, ST + br * 128);
        k_bnapply<<<NN * 16 / 256, 256>>>(Z, ST + br * 128, mlpg + br * FF, mlpbe + br * FF,
                                          (br == 0) ? x : nullptr, batch, XACC, POOL,
                                          (br == 3) ? 1 : 0);
    }

    // ---- fused head ----
    k_head<<<1, 1024, (64 * 65 + 64 * 257 + 64 * 129) * sizeof(float)>>>(
        POOL, fc1W, fc1b, fc1g, fc1be, fc2W, fc2b, fc2g, fc2be,
        fc3W, fc3b, fc3g, fc3be, out);
}

// round 12
// speedup vs baseline: 1.1075x; 1.1075x over previous
#include <cuda_runtime.h>
#include <math.h>

#define NN 32768
#define FF 64
#define HH 4
#define HFD 256
#define ESZ 524288
#define EGZ 524288
#define GG 64
#define NCC 10
#define BNEPS 1e-5f

// ---------------- float scratch arena ----------------------------------------
#define O_B0     0
#define O_BR     (O_B0 + NN*FF)
#define O_X      (O_BR + 3*NN*FF)
#define O_H      (O_X + 3*NN*FF)
#define O_ATT    (O_H + NN*HFD)
#define O_AS     (O_ATT + NN*HFD)
#define O_AD     (O_AS + NN*HH)
#define O_AEX    (O_AD + NN*HH)
#define O_SEXP   (O_AEX + EGZ*HH)
#define O_INV    (O_SEXP + NN*HH)
#define O_C0A    (O_INV + NN*HH)
#define O_Z      (O_C0A + ESZ)
#define O_XACC   (O_Z + NN*FF)
#define O_STATS  (O_XACC + NN*FF)
#define O_POOL   (O_STATS + 512)
#define ARENA_SZ (O_POOL + GG*FF)

__device__ __align__(256) float g_arena[ARENA_SZ];

// ---------------- int scratch arena -------------------------------------------
#define I_DEGE 0
#define I_CURE (I_DEGE + NN)
#define I_RPE  (I_CURE + NN)
#define I_CSRE (I_RPE + NN)
#define I_DEG0 (I_CSRE + EGZ)
#define I_CUR0 (I_DEG0 + NN)
#define I_RP0  (I_CUR0 + NN)
#define I_CSR0 (I_RP0 + NN)
#define I_BSUM (I_CSR0 + ESZ)
#define IARENA_SZ (I_BSUM + 128)

__device__ __align__(256) int g_iarena[IARENA_SZ];

// ---------------- helpers -----------------------------------------------------
__device__ __forceinline__ void red4(float* a, float4 v) {
    asm volatile("red.global.add.v4.f32 [%0], {%1,%2,%3,%4};"
                 :: "l"(a), "f"(v.x), "f"(v.y), "f"(v.z), "f"(v.w) : "memory");
}
__device__ __forceinline__ float lrelu(float v) { return v > 0.f ? v : 0.2f * v; }
__device__ __forceinline__ float eluf(float v)  { return v > 0.f ? v : __expf(v) - 1.f; }
__device__ __forceinline__ float tf32r(float f) {
    unsigned o;
    asm("cvt.rna.tf32.f32 %0, %1;" : "=r"(o) : "f"(f));
    return __uint_as_float(o);
}
__device__ __forceinline__ void mma8(float* d, float a0, float a1, float a2, float a3,
                                     float b0, float b1) {
    asm volatile(
        "mma.sync.aligned.m16n8k8.row.col.f32.tf32.tf32.f32 "
        "{%0,%1,%2,%3}, {%4,%5,%6,%7}, {%8,%9}, {%0,%1,%2,%3};"
        : "+f"(d[0]), "+f"(d[1]), "+f"(d[2]), "+f"(d[3])
        : "r"(__float_as_uint(a0)), "r"(__float_as_uint(a1)),
          "r"(__float_as_uint(a2)), "r"(__float_as_uint(a3)),
          "r"(__float_as_uint(b0)), "r"(__float_as_uint(b1)));
}

// ---------------- CSR build ---------------------------------------------------
__global__ __launch_bounds__(256) void k_hist(const int* __restrict__ dst, int* __restrict__ deg)
{
    int e = blockIdx.x * 256 + threadIdx.x;
    atomicAdd(&deg[dst[e]], 1);
}

__global__ __launch_bounds__(256) void k_blocksum(
    const int* __restrict__ deg, int* __restrict__ bsum)
{
    __shared__ int sh[256];
    int t = threadIdx.x;
    sh[t] = deg[blockIdx.x * 256 + t];
    __syncthreads();
#pragma unroll
    for (int off = 128; off; off >>= 1) {
        if (t < off) sh[t] += sh[t + off];
        __syncthreads();
    }
    if (t == 0) bsum[blockIdx.x] = sh[0];
}

__global__ __launch_bounds__(128) void k_scanbs(int* __restrict__ bsum)
{
    __shared__ int sh[128];
    int t = threadIdx.x;
    int v = bsum[t];
    sh[t] = v;
    __syncthreads();
#pragma unroll
    for (int off = 1; off < 128; off <<= 1) {
        int u = (t >= off) ? sh[t - off] : 0;
        __syncthreads();
        sh[t] += u;
        __syncthreads();
    }
    bsum[t] = sh[t] - v;
}

__global__ __launch_bounds__(256) void k_scanout(
    const int* __restrict__ deg, const int* __restrict__ bsum,
    int* __restrict__ rowptr, int* __restrict__ cur)
{
    __shared__ int sh[256];
    int t = threadIdx.x;
    int g = blockIdx.x * 256 + t;
    int v = deg[g];
    sh[t] = v;
    __syncthreads();
#pragma unroll
    for (int off = 1; off < 256; off <<= 1) {
        int u = (t >= off) ? sh[t - off] : 0;
        __syncthreads();
        sh[t] += u;
        __syncthreads();
    }
    int ex = sh[t] - v + bsum[blockIdx.x];
    rowptr[g] = ex;
    cur[g] = ex;
}

__global__ __launch_bounds__(256) void k_fillE(
    const int* __restrict__ ei, int* __restrict__ cur, int* __restrict__ csr)
{
    int e = blockIdx.x * 256 + threadIdx.x;
    int d = ei[EGZ + e];
    int p = atomicAdd(&cur[d], 1);
    csr[p] = ei[e];
}

__global__ __launch_bounds__(256) void k_fill0(
    const int* __restrict__ si, const float* __restrict__ sattr,
    int* __restrict__ cur, int* __restrict__ csr, float* __restrict__ csra)
{
    int e = blockIdx.x * 256 + threadIdx.x;
    int d = si[ESZ + e];
    int p = atomicAdd(&cur[d], 1);
    csr[p] = si[e];
    csra[p] = sattr[e];
}

// ---------------- merged atomic scatter (3 passes via grid.y) -----------------
__global__ __launch_bounds__(256) void k_scatter3(
    const int* __restrict__ sidx, const float* __restrict__ sattr,
    const float* __restrict__ xin, float* __restrict__ brout)
{
    int j = blockIdx.y + 1;
    const int* src  = sidx + j * 2 * ESZ;
    const int* dst  = src + ESZ;
    const float* at = sattr + j * ESZ;
    float* outb = brout + (size_t)(j - 1) * NN * FF;

    int t = blockIdx.x * 256 + threadIdx.x;
    int e = t >> 4, lane = t & 15;
    int s = src[e], d = dst[e];
    float a = at[e];
    float4 v = ((const float4*)xin)[s * 16 + lane];
    v.x *= a; v.y *= a; v.z *= a; v.w *= a;
    red4(outb + d * 64 + lane * 4, v);
}

// ---------------- merged CSR gathers (4 via grid.y) ---------------------------
__global__ __launch_bounds__(256) void k_gather4(
    const int* __restrict__ rowptr, const int* __restrict__ deg,
    const int* __restrict__ csr, const float* __restrict__ csra,
    const float* __restrict__ x, const float* __restrict__ brin,
    float* __restrict__ b0out, float* __restrict__ xout)
{
    int br = blockIdx.y;
    const float* xin = (br == 0) ? x : brin + (size_t)(br - 1) * NN * FF;
    float* outb = (br == 0) ? b0out : xout + (size_t)(br - 1) * NN * FF;
    int doAbs = (br > 0);

    int t = blockIdx.x * 256 + threadIdx.x;
    int n = t >> 4, q = t & 15;
    int b = rowptr[n], dg = deg[n];
    float4 acc = make_float4(0.f, 0.f, 0.f, 0.f);
    const float4* xin4 = (const float4*)xin;
    for (int p = b; p < b + dg; p++) {
        int s = csr[p];
        float a = csra[p];
        float4 v = xin4[s * 16 + q];
        if (doAbs) { v.x = fabsf(v.x); v.y = fabsf(v.y); v.z = fabsf(v.z); v.w = fabsf(v.w); }
        acc.x += a * v.x; acc.y += a * v.y; acc.z += a * v.z; acc.w += a * v.w;
    }
    ((float4*)outb)[n * 16 + q] = acc;
}

// ---------------- GEMM1 3xTF32 mma + fused attcoef ----------------------------
// h[64rows,256] = xin[64,64] @ W[64,256]; as_/ad_ fused.
// smem holds raw fp32; hi/lo split done at fragment load.
__global__ __launch_bounds__(256) void k_gemm_h_mma(
    const float* __restrict__ xin, const float* __restrict__ W,
    const float* __restrict__ asrc, const float* __restrict__ adst,
    float* __restrict__ h, float* __restrict__ as_, float* __restrict__ ad_)
{
    extern __shared__ float sm1[];
    float* As = sm1;              // 64 x 68
    float* Ws = sm1 + 64 * 68;    // 64 x 264
    int t = threadIdx.x;
    int row0 = blockIdx.x * 64;

    for (int i = t; i < 64 * 16; i += 256) {
        int r = i >> 4, c4 = i & 15;
        float4 v = ((const float4*)(xin + (size_t)(row0 + r) * 64))[c4];
        float* dp = &As[r * 68 + c4 * 4];
        dp[0] = v.x; dp[1] = v.y; dp[2] = v.z; dp[3] = v.w;
    }
    const float4* W4 = (const float4*)W;
    for (int i = t; i < 64 * 64; i += 256) {
        int r = i >> 6, c4 = i & 63;
        float4 v = W4[r * 64 + c4];
        float* dp = &Ws[r * 264 + c4 * 4];
        dp[0] = v.x; dp[1] = v.y; dp[2] = v.z; dp[3] = v.w;
    }
    __syncthreads();

    int wid = t >> 5, lane = t & 31;
    int wm = wid & 3, wn = wid >> 2;
    int g = lane >> 2, tg = lane & 3;

    float acc[16][4];
#pragma unroll
    for (int nt = 0; nt < 16; nt++)
#pragma unroll
        for (int c = 0; c < 4; c++) acc[nt][c] = 0.f;

#pragma unroll
    for (int k8 = 0; k8 < 8; k8++) {
        int kb = k8 * 8;
        float v0 = As[(wm * 16 + g) * 68 + kb + tg];
        float v1 = As[(wm * 16 + g + 8) * 68 + kb + tg];
        float v2 = As[(wm * 16 + g) * 68 + kb + tg + 4];
        float v3 = As[(wm * 16 + g + 8) * 68 + kb + tg + 4];
        float ah0 = tf32r(v0), ah1 = tf32r(v1), ah2 = tf32r(v2), ah3 = tf32r(v3);
        float al0 = tf32r(v0 - ah0), al1 = tf32r(v1 - ah1);
        float al2 = tf32r(v2 - ah2), al3 = tf32r(v3 - ah3);
#pragma unroll
        for (int nt = 0; nt < 16; nt++) {
            int n0 = wn * 128 + nt * 8;
            float w0 = Ws[(kb + tg) * 264 + n0 + g];
            float w1 = Ws[(kb + tg + 4) * 264 + n0 + g];
            float bh0 = tf32r(w0), bh1 = tf32r(w1);
            float bl0 = tf32r(w0 - bh0), bl1 = tf32r(w1 - bh1);
            mma8(acc[nt], al0, al1, al2, al3, bh0, bh1);
            mma8(acc[nt], ah0, ah1, ah2, ah3, bl0, bl1);
            mma8(acc[nt], ah0, ah1, ah2, ah3, bh0, bh1);
        }
    }

    // store h
    int r0 = row0 + wm * 16 + g;
    int r1 = r0 + 8;
#pragma unroll
    for (int nt = 0; nt < 16; nt++) {
        int n0 = wn * 128 + nt * 8 + tg * 2;
        *(float2*)&h[(size_t)r0 * 256 + n0] = make_float2(acc[nt][0], acc[nt][1]);
        *(float2*)&h[(size_t)r1 * 256 + n0] = make_float2(acc[nt][2], acc[nt][3]);
    }

    // fused attcoef: heads wn*2 and wn*2+1
    float sa[2][2] = {{0.f, 0.f}, {0.f, 0.f}};
    float sd[2][2] = {{0.f, 0.f}, {0.f, 0.f}};
#pragma unroll
    for (int nt = 0; nt < 16; nt++) {
        int hsel = nt >> 3;
        int hd = wn * 2 + hsel;
        int cm = (nt & 7) * 8 + tg * 2;
        float wa0 = asrc[hd * 64 + cm], wa1 = asrc[hd * 64 + cm + 1];
        float wd0 = adst[hd * 64 + cm], wd1 = adst[hd * 64 + cm + 1];
        sa[hsel][0] += acc[nt][0] * wa0 + acc[nt][1] * wa1;
        sa[hsel][1] += acc[nt][2] * wa0 + acc[nt][3] * wa1;
        sd[hsel][0] += acc[nt][0] * wd0 + acc[nt][1] * wd1;
        sd[hsel][1] += acc[nt][2] * wd0 + acc[nt][3] * wd1;
    }
#pragma unroll
    for (int o = 1; o <= 2; o <<= 1) {
#pragma unroll
        for (int hs = 0; hs < 2; hs++)
#pragma unroll
            for (int rr = 0; rr < 2; rr++) {
                sa[hs][rr] += __shfl_xor_sync(0xffffffffu, sa[hs][rr], o);
                sd[hs][rr] += __shfl_xor_sync(0xffffffffu, sd[hs][rr], o);
            }
    }
    if (tg == 0) {
        as_[r0 * 4 + wn * 2 + 0] = sa[0][0];
        as_[r1 * 4 + wn * 2 + 0] = sa[0][1];
        as_[r0 * 4 + wn * 2 + 1] = sa[1][0];
        as_[r1 * 4 + wn * 2 + 1] = sa[1][1];
        ad_[r0 * 4 + wn * 2 + 0] = sd[0][0];
        ad_[r1 * 4 + wn * 2 + 0] = sd[0][1];
        ad_[r0 * 4 + wn * 2 + 1] = sd[1][0];
        ad_[r1 * 4 + wn * 2 + 1] = sd[1][1];
    }
}

// ---------------- GEMM2 3xTF32 mma + fused BN stats ---------------------------
__global__ __launch_bounds__(256) void k_gemm_z_mma(
    const float* __restrict__ att, const float* __restrict__ bias,
    const float* __restrict__ W, float* __restrict__ z, float* __restrict__ stats)
{
    __shared__ float As[64 * 68];
    __shared__ float Ws[64 * 72];
    __shared__ float ssum[64], ssq[64];
    int t = threadIdx.x;
    int row0 = blockIdx.x * 64;
    if (t < 64) { ssum[t] = 0.f; ssq[t] = 0.f; }

    int wid = t >> 5, lane = t & 31;
    int wm = wid & 3, wn = wid >> 2;
    int g = lane >> 2, tg = lane & 3;

    float acc[4][4];
#pragma unroll
    for (int nt = 0; nt < 4; nt++)
#pragma unroll
        for (int c = 0; c < 4; c++) acc[nt][c] = 0.f;

    const float4* att4 = (const float4*)att;
    const float4* bias4 = (const float4*)bias;
    const float4* W4 = (const float4*)W;

    for (int kc = 0; kc < 4; kc++) {
        __syncthreads();
        for (int i = t; i < 64 * 16; i += 256) {
            int r = i >> 4, c4 = i & 15;
            float4 v = att4[(size_t)(row0 + r) * 64 + kc * 16 + c4];
            float4 b = bias4[kc * 16 + c4];
            float* dp = &As[r * 68 + c4 * 4];
            dp[0] = eluf(v.x + b.x); dp[1] = eluf(v.y + b.y);
            dp[2] = eluf(v.z + b.z); dp[3] = eluf(v.w + b.w);
        }
        for (int i = t; i < 64 * 16; i += 256) {
            int r = i >> 4, c4 = i & 15;
            float4 v = W4[(size_t)(kc * 64 + r) * 16 + c4];
            float* dp = &Ws[r * 72 + c4 * 4];
            dp[0] = v.x; dp[1] = v.y; dp[2] = v.z; dp[3] = v.w;
        }
        __syncthreads();
#pragma unroll
        for (int k8 = 0; k8 < 8; k8++) {
            int kb = k8 * 8;
            float v0 = As[(wm * 16 + g) * 68 + kb + tg];
            float v1 = As[(wm * 16 + g + 8) * 68 + kb + tg];
            float v2 = As[(wm * 16 + g) * 68 + kb + tg + 4];
            float v3 = As[(wm * 16 + g + 8) * 68 + kb + tg + 4];
            float ah0 = tf32r(v0), ah1 = tf32r(v1), ah2 = tf32r(v2), ah3 = tf32r(v3);
            float al0 = tf32r(v0 - ah0), al1 = tf32r(v1 - ah1);
            float al2 = tf32r(v2 - ah2), al3 = tf32r(v3 - ah3);
#pragma unroll
            for (int nt = 0; nt < 4; nt++) {
                int n0 = wn * 32 + nt * 8;
                float w0 = Ws[(kb + tg) * 72 + n0 + g];
                float w1 = Ws[(kb + tg + 4) * 72 + n0 + g];
                float bh0 = tf32r(w0), bh1 = tf32r(w1);
                float bl0 = tf32r(w0 - bh0), bl1 = tf32r(w1 - bh1);
                mma8(acc[nt], al0, al1, al2, al3, bh0, bh1);
                mma8(acc[nt], ah0, ah1, ah2, ah3, bl0, bl1);
                mma8(acc[nt], ah0, ah1, ah2, ah3, bh0, bh1);
            }
        }
    }

    int r0 = row0 + wm * 16 + g;
    int r1 = r0 + 8;
#pragma unroll
    for (int nt = 0; nt < 4; nt++) {
        int c = wn * 32 + nt * 8 + tg * 2;
        *(float2*)&z[(size_t)r0 * 64 + c] = make_float2(acc[nt][0], acc[nt][1]);
        *(float2*)&z[(size_t)r1 * 64 + c] = make_float2(acc[nt][2], acc[nt][3]);
        atomicAdd(&ssum[c],     acc[nt][0] + acc[nt][2]);
        atomicAdd(&ssum[c + 1], acc[nt][1] + acc[nt][3]);
        atomicAdd(&ssq[c],      acc[nt][0] * acc[nt][0] + acc[nt][2] * acc[nt][2]);
        atomicAdd(&ssq[c + 1],  acc[nt][1] * acc[nt][1] + acc[nt][3] * acc[nt][3]);
    }
    __syncthreads();
    if (t < 64) {
        atomicAdd(&stats[t], ssum[t]);
        atomicAdd(&stats[FF + t], ssq[t]);
    }
}

// ---------------- per-node softmax over CSR (warp/node) -----------------------
__global__ __launch_bounds__(256) void k_softmax(
    const int* __restrict__ rowptr, const int* __restrict__ deg, const int* __restrict__ csr,
    const float* __restrict__ as_, const float* __restrict__ ad_,
    float* __restrict__ aex, float* __restrict__ sexp, float* __restrict__ inv)
{
    int n = blockIdx.x * 8 + (threadIdx.x >> 5);
    int lane = threadIdx.x & 31;
    int b = rowptr[n], dg = deg[n];
    float4 adn = ((const float4*)ad_)[n];
    float4 asn = ((const float4*)as_)[n];
    float4 self;
    self.x = lrelu(asn.x + adn.x); self.y = lrelu(asn.y + adn.y);
    self.z = lrelu(asn.z + adn.z); self.w = lrelu(asn.w + adn.w);

    float4 mx = self;
    for (int j = lane; j < dg; j += 32) {
        float4 sv = ((const float4*)as_)[csr[b + j]];
        mx.x = fmaxf(mx.x, lrelu(sv.x + adn.x));
        mx.y = fmaxf(mx.y, lrelu(sv.y + adn.y));
        mx.z = fmaxf(mx.z, lrelu(sv.z + adn.z));
        mx.w = fmaxf(mx.w, lrelu(sv.w + adn.w));
    }
#pragma unroll
    for (int o = 16; o; o >>= 1) {
        mx.x = fmaxf(mx.x, __shfl_xor_sync(0xffffffffu, mx.x, o));
        mx.y = fmaxf(mx.y, __shfl_xor_sync(0xffffffffu, mx.y, o));
        mx.z = fmaxf(mx.z, __shfl_xor_sync(0xffffffffu, mx.z, o));
        mx.w = fmaxf(mx.w, __shfl_xor_sync(0xffffffffu, mx.w, o));
    }

    float4 sum = make_float4(0.f, 0.f, 0.f, 0.f);
    for (int j = lane; j < dg; j += 32) {
        float4 sv = ((const float4*)as_)[csr[b + j]];
        float4 ex;
        ex.x = __expf(lrelu(sv.x + adn.x) - mx.x);
        ex.y = __expf(lrelu(sv.y + adn.y) - mx.y);
        ex.z = __expf(lrelu(sv.z + adn.z) - mx.z);
        ex.w = __expf(lrelu(sv.w + adn.w) - mx.w);
        ((float4*)aex)[b + j] = ex;
        sum.x += ex.x; sum.y += ex.y; sum.z += ex.z; sum.w += ex.w;
    }
#pragma unroll
    for (int o = 16; o; o >>= 1) {
        sum.x += __shfl_xor_sync(0xffffffffu, sum.x, o);
        sum.y += __shfl_xor_sync(0xffffffffu, sum.y, o);
        sum.z += __shfl_xor_sync(0xffffffffu, sum.z, o);
        sum.w += __shfl_xor_sync(0xffffffffu, sum.w, o);
    }
    if (lane == 0) {
        float4 sex;
        sex.x = __expf(self.x - mx.x); sex.y = __expf(self.y - mx.y);
        sex.z = __expf(self.z - mx.z); sex.w = __expf(self.w - mx.w);
        float4 iv;
        iv.x = 1.f / (sum.x + sex.x); iv.y = 1.f / (sum.y + sex.y);
        iv.z = 1.f / (sum.z + sex.z); iv.w = 1.f / (sum.w + sex.w);
        ((float4*)sexp)[n] = sex;
        ((float4*)inv)[n] = iv;
    }
}

// ---------------- CSR gather aggregation --------------------------------------
__global__ __launch_bounds__(256) void k_aggr(
    const int* __restrict__ rowptr, const int* __restrict__ deg, const int* __restrict__ csr,
    const float* __restrict__ aex, const float* __restrict__ sexp, const float* __restrict__ inv,
    const float* __restrict__ h, float* __restrict__ att)
{
    int t = blockIdx.x * 256 + threadIdx.x;
    int n = t >> 6, gq = t & 63, hd = gq >> 4;
    int b = rowptr[n], dg = deg[n];
    float sex = sexp[n * 4 + hd];
    float iv  = inv[n * 4 + hd];
    const float4* h4 = (const float4*)h;
    float4 acc = h4[(size_t)n * 64 + gq];
    acc.x *= sex; acc.y *= sex; acc.z *= sex; acc.w *= sex;
    for (int p = b; p < b + dg; p++) {
        int s = csr[p];
        float al = aex[p * 4 + hd];
        float4 hv = h4[(size_t)s * 64 + gq];
        acc.x += al * hv.x; acc.y += al * hv.y;
        acc.z += al * hv.z; acc.w += al * hv.w;
    }
    acc.x *= iv; acc.y *= iv; acc.z *= iv; acc.w *= iv;
    ((float4*)att)[(size_t)n * 64 + gq] = acc;
}

// ---------------- BN apply (fused finstats; init / accumulate / pool) ---------
__global__ __launch_bounds__(256) void k_bnapply(
    const float* __restrict__ z, const float* __restrict__ stats,
    const float* __restrict__ g, const float* __restrict__ be,
    const float* __restrict__ base, const int* __restrict__ batch,
    float* __restrict__ xacc, float* __restrict__ pool, int doPool)
{
    __shared__ float sm_mu[64], sm_rs[64], sm_b[64];
    int t = threadIdx.x;
    if (t < 64) {
        float mu = stats[t] * (1.f / NN);
        float var = stats[FF + t] * (1.f / NN) - mu * mu;
        sm_mu[t] = mu;
        sm_rs[t] = rsqrtf(var + BNEPS) * g[t];
        sm_b[t] = be[t];
    }
    __syncthreads();
    int gidx = blockIdx.x * 256 + t;
    int n = gidx >> 4, q = gidx & 15, f0 = q * 4;
    float4 zv = ((const float4*)z)[gidx];
    float4 v;
    v.x = (zv.x - sm_mu[f0 + 0]) * sm_rs[f0 + 0] + sm_b[f0 + 0];
    v.y = (zv.y - sm_mu[f0 + 1]) * sm_rs[f0 + 1] + sm_b[f0 + 1];
    v.z = (zv.z - sm_mu[f0 + 2]) * sm_rs[f0 + 2] + sm_b[f0 + 2];
    v.w = (zv.w - sm_mu[f0 + 3]) * sm_rs[f0 + 3] + sm_b[f0 + 3];
    float4 bv;
    if (base) bv = ((const float4*)base)[gidx];
    else      bv = ((const float4*)xacc)[gidx];
    v.x += bv.x; v.y += bv.y; v.z += bv.z; v.w += bv.w;
    ((float4*)xacc)[gidx] = v;
    if (doPool) red4(pool + batch[n] * 64 + f0, v);
}

// ---------------- fused FC head (single block, 1024 threads) ------------------
__global__ __launch_bounds__(1024) void k_head(
    const float* __restrict__ pool,
    const float* __restrict__ fc1W, const float* __restrict__ fc1b,
    const float* __restrict__ fc1g, const float* __restrict__ fc1be,
    const float* __restrict__ fc2W, const float* __restrict__ fc2b,
    const float* __restrict__ fc2g, const float* __restrict__ fc2be,
    const float* __restrict__ fc3W, const float* __restrict__ fc3b,
    const float* __restrict__ fc3g, const float* __restrict__ fc3be,
    float* __restrict__ out)
{
    extern __shared__ float sm[];
    float* sp = sm;
    float* y1 = sp + 64 * 65;
    float* y2 = y1 + 64 * 257;
    int t = threadIdx.x;

    for (int i = t; i < 64 * 16; i += 1024) {
        int r = i >> 4, c4 = i & 15;
        float4 v = ((const float4*)pool)[i];
        float* dp = &sp[r * 65 + c4 * 4];
        dp[0] = v.x; dp[1] = v.y; dp[2] = v.z; dp[3] = v.w;
    }
    __syncthreads();

    {
        int c = t & 255, rg = t >> 8;
        float accv[16];
        float bb = fc1b[c];
#pragma unroll
        for (int r = 0; r < 16; r++) accv[r] = bb;
        for (int k = 0; k < 64; k++) {
            float w = fc1W[k * 256 + c];
#pragma unroll
            for (int r = 0; r < 16; r++)
                accv[r] += sp[(rg * 16 + r) * 65 + k] * w;
        }
#pragma unroll
        for (int r = 0; r < 16; r++) y1[(rg * 16 + r) * 257 + c] = accv[r];
    }
    __syncthreads();
    if (t < 256) {
        float s = 0.f, ss = 0.f;
#pragma unroll 8
        for (int r = 0; r < 64; r++) { float v = y1[r * 257 + t]; s += v; ss += v * v; }
        float mu = s * (1.f / GG);
        float var = ss * (1.f / GG) - mu * mu;
        sp[t] = mu;
        sp[256 + t] = rsqrtf(var + BNEPS) * fc1g[t];
    }
    __syncthreads();
    for (int i = t; i < 64 * 256; i += 1024) {
        int r = i >> 8, c = i & 255;
        float v = (y1[r * 257 + c] - sp[c]) * sp[256 + c] + fc1be[c];
        y1[r * 257 + c] = fmaxf(v, 0.f);
    }
    __syncthreads();

    {
        int c = t & 127, rg = t >> 7;
        float accv[8];
        float bb = fc2b[c];
#pragma unroll
        for (int r = 0; r < 8; r++) accv[r] = bb;
        for (int k = 0; k < 256; k++) {
            float w = fc2W[k * 128 + c];
#pragma unroll
            for (int r = 0; r < 8; r++)
                accv[r] += y1[(rg * 8 + r) * 257 + k] * w;
        }
#pragma unroll
        for (int r = 0; r < 8; r++) y2[(rg * 8 + r) * 129 + c] = accv[r];
    }
    __syncthreads();
    if (t < 128) {
        float s = 0.f, ss = 0.f;
#pragma unroll 8
        for (int r = 0; r < 64; r++) { float v = y2[r * 129 + t]; s += v; ss += v * v; }
        float mu = s * (1.f / GG);
        float var = ss * (1.f / GG) - mu * mu;
        sp[t] = mu;
        sp[256 + t] = rsqrtf(var + BNEPS) * fc2g[t];
    }
    __syncthreads();
    for (int i = t; i < 64 * 128; i += 1024) {
        int r = i >> 7, c = i & 127;
        float v = (y2[r * 129 + c] - sp[c]) * sp[256 + c] + fc2be[c];
        y2[r * 129 + c] = fmaxf(v, 0.f);
    }
    __syncthreads();

    float* y3 = sp + 1024;
    if (t < 640) {
        int r = t / NCC, c = t % NCC;
        float acc = fc3b[c];
        for (int k = 0; k < 128; k++)
            acc += y2[r * 129 + k] * fc3W[k * NCC + c];
        y3[r * NCC + c] = acc;
    }
    __syncthreads();
    if (t < NCC) {
        float s = 0.f, ss = 0.f;
#pragma unroll 8
        for (int r = 0; r < 64; r++) { float v = y3[r * NCC + t]; s += v; ss += v * v; }
        float mu = s * (1.f / GG);
        float var = ss * (1.f / GG) - mu * mu;
        sp[t] = mu;
        sp[64 + t] = rsqrtf(var + BNEPS) * fc3g[t];
    }
    __syncthreads();
    if (t < 640) {
        int r = t / NCC, c = t % NCC;
        out[t] = (y3[r * NCC + c] - sp[c]) * sp[64 + c] + fc3be[c];
    }
}

// ---------------- host orchestration ------------------------------------------
extern "C" void kernel_launch(void* const* d_in, const int* in_sizes, int n_in,
                              void* d_out, int out_size)
{
    const float* x      = (const float*)d_in[0];
    const int*   eidx   = (const int*)d_in[1];
    const int*   batch  = (const int*)d_in[2];
    const int*   sidx   = (const int*)d_in[3];
    const float* sattr  = (const float*)d_in[4];
    const float* gatW   = (const float*)d_in[5];
    const float* gasrc  = (const float*)d_in[6];
    const float* gadst  = (const float*)d_in[7];
    const float* gatb   = (const float*)d_in[8];
    const float* mlpW   = (const float*)d_in[9];
    const float* mlpg   = (const float*)d_in[11];
    const float* mlpbe  = (const float*)d_in[12];
    const float* fc1W   = (const float*)d_in[13];
    const float* fc1b   = (const float*)d_in[14];
    const float* fc1g   = (const float*)d_in[15];
    const float* fc1be  = (const float*)d_in[16];
    const float* fc2W   = (const float*)d_in[17];
    const float* fc2b   = (const float*)d_in[18];
    const float* fc2g   = (const float*)d_in[19];
    const float* fc2be  = (const float*)d_in[20];
    const float* fc3W   = (const float*)d_in[21];
    const float* fc3b   = (const float*)d_in[22];
    const float* fc3g   = (const float*)d_in[23];
    const float* fc3be  = (const float*)d_in[24];
    float* out = (float*)d_out;

    float* A;
    cudaGetSymbolAddress((void**)&A, g_arena);
    int* IA;
    cudaGetSymbolAddress((void**)&IA, g_iarena);

    float* B0   = A + O_B0;
    float* BR   = A + O_BR;
    float* X123 = A + O_X;
    float* H    = A + O_H;
    float* ATT  = A + O_ATT;
    float* AS   = A + O_AS;
    float* AD   = A + O_AD;
    float* AEX  = A + O_AEX;
    float* SEXP = A + O_SEXP;
    float* INV  = A + O_INV;
    float* C0A  = A + O_C0A;
    float* Z    = A + O_Z;
    float* XACC = A + O_XACC;
    float* ST   = A + O_STATS;
    float* POOL = A + O_POOL;

    int* DEGE = IA + I_DEGE;
    int* CURE = IA + I_CURE;
    int* RPE  = IA + I_RPE;
    int* CSRE = IA + I_CSRE;
    int* DEG0 = IA + I_DEG0;
    int* CUR0 = IA + I_CUR0;
    int* RP0  = IA + I_RP0;
    int* CSR0 = IA + I_CSR0;
    int* BSUM = IA + I_BSUM;

    static int configured = 0;
    if (!configured) {
        cudaFuncSetAttribute(k_head, cudaFuncAttributeMaxDynamicSharedMemorySize, 120 * 1024);
        cudaFuncSetAttribute(k_gemm_h_mma, cudaFuncAttributeMaxDynamicSharedMemorySize, 90 * 1024);
        configured = 1;
    }

    // ---- CSR builds ----
    cudaMemsetAsync(DEGE, 0, NN * sizeof(int));
    cudaMemsetAsync(DEG0, 0, NN * sizeof(int));
    cudaMemsetAsync(ST, 0, 512 * sizeof(float));
    cudaMemsetAsync(POOL, 0, (size_t)GG * FF * sizeof(float));
    cudaMemsetAsync(BR, 0, (size_t)3 * NN * FF * sizeof(float));
    k_hist<<<EGZ / 256, 256>>>(eidx + EGZ, DEGE);
    k_hist<<<ESZ / 256, 256>>>(sidx + ESZ, DEG0);
    k_blocksum<<<NN / 256, 256>>>(DEGE, BSUM);
    k_scanbs<<<1, 128>>>(BSUM);
    k_scanout<<<NN / 256, 256>>>(DEGE, BSUM, RPE, CURE);
    k_fillE<<<EGZ / 256, 256>>>(eidx, CURE, CSRE);
    k_blocksum<<<NN / 256, 256>>>(DEG0, BSUM);
    k_scanbs<<<1, 128>>>(BSUM);
    k_scanout<<<NN / 256, 256>>>(DEG0, BSUM, RP0, CUR0);
    k_fill0<<<ESZ / 256, 256>>>(sidx, sattr, CUR0, CSR0, C0A);

    // ---- scatter stage (merged) ----
    dim3 sg(ESZ * 16 / 256, 3);
    k_scatter3<<<sg, 256>>>(sidx, sattr, x, BR);
    dim3 gg(NN * 16 / 256, 4);
    k_gather4<<<gg, 256>>>(RP0, DEG0, CSR0, C0A, x, BR, B0, X123);

    const float* bx[4] = { B0, X123, X123 + NN * FF, X123 + 2 * NN * FF };

    const int smem1 = (64 * 68 + 64 * 264) * sizeof(float);

    // ---- 4 GAT branches ----
    for (int br = 0; br < 4; br++) {
        k_gemm_h_mma<<<NN / 64, 256, smem1>>>(bx[br], gatW + br * FF * HFD,
                                              gasrc + br * HH * FF, gadst + br * HH * FF,
                                              H, AS, AD);
        k_softmax<<<NN / 8, 256>>>(RPE, DEGE, CSRE, AS, AD, AEX, SEXP, INV);
        k_aggr<<<NN * 64 / 256, 256>>>(RPE, DEGE, CSRE, AEX, SEXP, INV, H, ATT);
        k_gemm_z_mma<<<NN / 64, 256>>>(ATT, gatb + br * HFD, mlpW + br * HFD * FF, Z, ST + br * 128);
        k_bnapply<<<NN * 16 / 256, 256>>>(Z, ST + br * 128, mlpg + br * FF, mlpbe + br * FF,
                                          (br == 0) ? x : nullptr, batch, XACC, POOL,
                                          (br == 3) ? 1 : 0);
    }

    // ---- fused head ----
    k_head<<<1, 1024, (64 * 65 + 64 * 257 + 64 * 129) * sizeof(float)>>>(
        POOL, fc1W, fc1b, fc1g, fc1be, fc2W, fc2b, fc2g, fc2be,
        fc3W, fc3b, fc3g, fc3be, out);
}

// round 16
// speedup vs baseline: 1.1736x; 1.0597x over previous
#include <cuda_runtime.h>
#include <math.h>

#define NN 32768
#define FF 64
#define HH 4
#define HFD 256
#define ESZ 524288
#define EGZ 524288
#define GG 64
#define NCC 10
#define BNEPS 1e-5f

// ---------------- float scratch arena ----------------------------------------
#define O_B0     0
#define O_BR     (O_B0 + NN*FF)
#define O_X      (O_BR + 3*NN*FF)
#define O_H      (O_X + 3*NN*FF)
#define O_ATT    (O_H + NN*HFD)
#define O_AS     (O_ATT + NN*HFD)
#define O_AD     (O_AS + NN*HH)
#define O_AEX    (O_AD + NN*HH)
#define O_SEXP   (O_AEX + EGZ*HH)
#define O_INV    (O_SEXP + NN*HH)
#define O_CA     (O_INV + NN*HH)       // csr attrs for scatter sets 0..3 [4*E]
#define O_Z      (O_CA + 4*ESZ)        // 4 branch z buffers
#define O_STATS  (O_Z + 4*NN*FF)
#define O_POOL   (O_STATS + 512)
#define ARENA_SZ (O_POOL + GG*FF)

__device__ __align__(256) float g_arena[ARENA_SZ];

// ---------------- int scratch arena -------------------------------------------
// 5 CSR sets: slot 0 = GAT edge graph (eidx), slots 1..4 = scatter idx 0..3
#define I_DEG  0
#define I_CUR  (I_DEG + 5*NN)
#define I_RP   (I_CUR + 5*NN)
#define I_CSRE (I_RP + 5*NN)
#define I_CSR0 (I_CSRE + EGZ)          // 4*E for scatter sets
#define I_BSUM (I_CSR0 + 4*ESZ)
#define IARENA_SZ (I_BSUM + 5*128)

__device__ __align__(256) int g_iarena[IARENA_SZ];

// ---------------- helpers -----------------------------------------------------
__device__ __forceinline__ void red4(float* a, float4 v) {
    asm volatile("red.global.add.v4.f32 [%0], {%1,%2,%3,%4};"
                 :: "l"(a), "f"(v.x), "f"(v.y), "f"(v.z), "f"(v.w) : "memory");
}
__device__ __forceinline__ float lrelu(float v) { return v > 0.f ? v : 0.2f * v; }
__device__ __forceinline__ float eluf(float v)  { return v > 0.f ? v : __expf(v) - 1.f; }
__device__ __forceinline__ float tf32r(float f) {
    unsigned o;
    asm("cvt.rna.tf32.f32 %0, %1;" : "=r"(o) : "f"(f));
    return __uint_as_float(o);
}
__device__ __forceinline__ void mma8(float* d, float a0, float a1, float a2, float a3,
                                     float b0, float b1) {
    asm volatile(
        "mma.sync.aligned.m16n8k8.row.col.f32.tf32.tf32.f32 "
        "{%0,%1,%2,%3}, {%4,%5,%6,%7}, {%8,%9}, {%0,%1,%2,%3};"
        : "+f"(d[0]), "+f"(d[1]), "+f"(d[2]), "+f"(d[3])
        : "r"(__float_as_uint(a0)), "r"(__float_as_uint(a1)),
          "r"(__float_as_uint(a2)), "r"(__float_as_uint(a3)),
          "r"(__float_as_uint(b0)), "r"(__float_as_uint(b1)));
}

// ---------------- CSR build (5 sets via grid.y) -------------------------------
__global__ __launch_bounds__(256) void k_hist5(
    const int* __restrict__ eidx, const int* __restrict__ sidx, int* __restrict__ DEG)
{
    int y = blockIdx.y;
    const int* dstp = (y == 0) ? (eidx + EGZ) : (sidx + (y - 1) * 2 * ESZ + ESZ);
    int e = blockIdx.x * 256 + threadIdx.x;
    atomicAdd(&DEG[y * NN + dstp[e]], 1);
}

__global__ __launch_bounds__(256) void k_blocksum5(
    const int* __restrict__ DEG, int* __restrict__ BSUM)
{
    __shared__ int sh[256];
    int y = blockIdx.y;
    int t = threadIdx.x;
    sh[t] = DEG[y * NN + blockIdx.x * 256 + t];
    __syncthreads();
#pragma unroll
    for (int off = 128; off; off >>= 1) {
        if (t < off) sh[t] += sh[t + off];
        __syncthreads();
    }
    if (t == 0) BSUM[y * 128 + blockIdx.x] = sh[0];
}

__global__ __launch_bounds__(128) void k_scanbs5(int* __restrict__ BSUM)
{
    __shared__ int sh[128];
    int* bsum = BSUM + blockIdx.x * 128;
    int t = threadIdx.x;
    int v = bsum[t];
    sh[t] = v;
    __syncthreads();
#pragma unroll
    for (int off = 1; off < 128; off <<= 1) {
        int u = (t >= off) ? sh[t - off] : 0;
        __syncthreads();
        sh[t] += u;
        __syncthreads();
    }
    bsum[t] = sh[t] - v;
}

__global__ __launch_bounds__(256) void k_scanout5(
    const int* __restrict__ DEG, const int* __restrict__ BSUM,
    int* __restrict__ RP, int* __restrict__ CUR)
{
    __shared__ int sh[256];
    int y = blockIdx.y;
    int t = threadIdx.x;
    int g = blockIdx.x * 256 + t;
    int v = DEG[y * NN + g];
    sh[t] = v;
    __syncthreads();
#pragma unroll
    for (int off = 1; off < 256; off <<= 1) {
        int u = (t >= off) ? sh[t - off] : 0;
        __syncthreads();
        sh[t] += u;
        __syncthreads();
    }
    int ex = sh[t] - v + BSUM[y * 128 + blockIdx.x];
    RP[y * NN + g] = ex;
    CUR[y * NN + g] = ex;
}

__global__ __launch_bounds__(256) void k_fillE(
    const int* __restrict__ ei, int* __restrict__ cur, int* __restrict__ csr)
{
    int e = blockIdx.x * 256 + threadIdx.x;
    int d = ei[EGZ + e];
    int p = atomicAdd(&cur[d], 1);
    csr[p] = ei[e];
}

// fill scatter CSRs 0..3 (grid.y = 4)
__global__ __launch_bounds__(256) void k_fillS(
    const int* __restrict__ sidx, const float* __restrict__ sattr,
    int* __restrict__ CUR, int* __restrict__ CSR0, float* __restrict__ CA)
{
    int j = blockIdx.y;
    const int* si = sidx + j * 2 * ESZ;
    const float* at = sattr + j * ESZ;
    int* cur = CUR + (j + 1) * NN;
    int* csr = CSR0 + j * ESZ;
    float* csra = CA + j * ESZ;
    int e = blockIdx.x * 256 + threadIdx.x;
    int d = si[ESZ + e];
    int p = atomicAdd(&cur[d], 1);
    csr[p] = si[e];
    csra[p] = at[e];
}

// ---------------- gather for scatter sets 1..3 (replaces RED scatter) ---------
__global__ __launch_bounds__(256) void k_gatherBR(
    const int* __restrict__ RP, const int* __restrict__ DEG,
    const int* __restrict__ CSR0, const float* __restrict__ CA,
    const float* __restrict__ x, float* __restrict__ brout)
{
    int j = blockIdx.y + 1;                      // scatter set 1..3
    const int* rowptr = RP + (j + 1) * NN;
    const int* deg = DEG + (j + 1) * NN;
    const int* csr = CSR0 + j * ESZ;
    const float* csra = CA + j * ESZ;
    float* outb = brout + (size_t)(j - 1) * NN * FF;

    int t = blockIdx.x * 256 + threadIdx.x;
    int n = t >> 4, q = t & 15;
    int b = rowptr[n], dg = deg[n];
    float4 acc = make_float4(0.f, 0.f, 0.f, 0.f);
    const float4* x4 = (const float4*)x;
    for (int p = b; p < b + dg; p++) {
        int s = csr[p];
        float a = csra[p];
        float4 v = x4[s * 16 + q];
        acc.x += a * v.x; acc.y += a * v.y; acc.z += a * v.z; acc.w += a * v.w;
    }
    ((float4*)outb)[n * 16 + q] = acc;
}

// ---------------- gathers with scatter-set-0 CSR (4 via grid.y) ---------------
__global__ __launch_bounds__(256) void k_gather4(
    const int* __restrict__ RP, const int* __restrict__ DEG,
    const int* __restrict__ CSR0, const float* __restrict__ CA,
    const float* __restrict__ x, const float* __restrict__ brin,
    float* __restrict__ b0out, float* __restrict__ xout)
{
    int br = blockIdx.y;
    const float* xin = (br == 0) ? x : brin + (size_t)(br - 1) * NN * FF;
    float* outb = (br == 0) ? b0out : xout + (size_t)(br - 1) * NN * FF;
    int doAbs = (br > 0);
    const int* rowptr = RP + NN;                 // set 0 lives in slot 1
    const int* deg = DEG + NN;
    const int* csr = CSR0;
    const float* csra = CA;

    int t = blockIdx.x * 256 + threadIdx.x;
    int n = t >> 4, q = t & 15;
    int b = rowptr[n], dg = deg[n];
    float4 acc = make_float4(0.f, 0.f, 0.f, 0.f);
    const float4* xin4 = (const float4*)xin;
    for (int p = b; p < b + dg; p++) {
        int s = csr[p];
        float a = csra[p];
        float4 v = xin4[s * 16 + q];
        if (doAbs) { v.x = fabsf(v.x); v.y = fabsf(v.y); v.z = fabsf(v.z); v.w = fabsf(v.w); }
        acc.x += a * v.x; acc.y += a * v.y; acc.z += a * v.z; acc.w += a * v.w;
    }
    ((float4*)outb)[n * 16 + q] = acc;
}

// ---------------- GEMM1 3xTF32 mma + fused attcoef ----------------------------
__global__ __launch_bounds__(256) void k_gemm_h_mma(
    const float* __restrict__ xin, const float* __restrict__ W,
    const float* __restrict__ asrc, const float* __restrict__ adst,
    float* __restrict__ h, float* __restrict__ as_, float* __restrict__ ad_)
{
    extern __shared__ float sm1[];
    float* As = sm1;              // 64 x 68
    float* Ws = sm1 + 64 * 68;    // 64 x 264
    int t = threadIdx.x;
    int row0 = blockIdx.x * 64;

    for (int i = t; i < 64 * 16; i += 256) {
        int r = i >> 4, c4 = i & 15;
        float4 v = ((const float4*)(xin + (size_t)(row0 + r) * 64))[c4];
        float* dp = &As[r * 68 + c4 * 4];
        dp[0] = v.x; dp[1] = v.y; dp[2] = v.z; dp[3] = v.w;
    }
    const float4* W4 = (const float4*)W;
    for (int i = t; i < 64 * 64; i += 256) {
        int r = i >> 6, c4 = i & 63;
        float4 v = W4[r * 64 + c4];
        float* dp = &Ws[r * 264 + c4 * 4];
        dp[0] = v.x; dp[1] = v.y; dp[2] = v.z; dp[3] = v.w;
    }
    __syncthreads();

    int wid = t >> 5, lane = t & 31;
    int wm = wid & 3, wn = wid >> 2;
    int g = lane >> 2, tg = lane & 3;

    float acc[16][4];
#pragma unroll
    for (int nt = 0; nt < 16; nt++)
#pragma unroll
        for (int c = 0; c < 4; c++) acc[nt][c] = 0.f;

#pragma unroll
    for (int k8 = 0; k8 < 8; k8++) {
        int kb = k8 * 8;
        float v0 = As[(wm * 16 + g) * 68 + kb + tg];
        float v1 = As[(wm * 16 + g + 8) * 68 + kb + tg];
        float v2 = As[(wm * 16 + g) * 68 + kb + tg + 4];
        float v3 = As[(wm * 16 + g + 8) * 68 + kb + tg + 4];
        float ah0 = tf32r(v0), ah1 = tf32r(v1), ah2 = tf32r(v2), ah3 = tf32r(v3);
        float al0 = tf32r(v0 - ah0), al1 = tf32r(v1 - ah1);
        float al2 = tf32r(v2 - ah2), al3 = tf32r(v3 - ah3);
#pragma unroll
        for (int nt = 0; nt < 16; nt++) {
            int n0 = wn * 128 + nt * 8;
            float w0 = Ws[(kb + tg) * 264 + n0 + g];
            float w1 = Ws[(kb + tg + 4) * 264 + n0 + g];
            float bh0 = tf32r(w0), bh1 = tf32r(w1);
            float bl0 = tf32r(w0 - bh0), bl1 = tf32r(w1 - bh1);
            mma8(acc[nt], al0, al1, al2, al3, bh0, bh1);
            mma8(acc[nt], ah0, ah1, ah2, ah3, bl0, bl1);
            mma8(acc[nt], ah0, ah1, ah2, ah3, bh0, bh1);
        }
    }

    int r0 = row0 + wm * 16 + g;
    int r1 = r0 + 8;
#pragma unroll
    for (int nt = 0; nt < 16; nt++) {
        int n0 = wn * 128 + nt * 8 + tg * 2;
        *(float2*)&h[(size_t)r0 * 256 + n0] = make_float2(acc[nt][0], acc[nt][1]);
        *(float2*)&h[(size_t)r1 * 256 + n0] = make_float2(acc[nt][2], acc[nt][3]);
    }

    float sa[2][2] = {{0.f, 0.f}, {0.f, 0.f}};
    float sd[2][2] = {{0.f, 0.f}, {0.f, 0.f}};
#pragma unroll
    for (int nt = 0; nt < 16; nt++) {
        int hsel = nt >> 3;
        int hd = wn * 2 + hsel;
        int cm = (nt & 7) * 8 + tg * 2;
        float wa0 = asrc[hd * 64 + cm], wa1 = asrc[hd * 64 + cm + 1];
        float wd0 = adst[hd * 64 + cm], wd1 = adst[hd * 64 + cm + 1];
        sa[hsel][0] += acc[nt][0] * wa0 + acc[nt][1] * wa1;
        sa[hsel][1] += acc[nt][2] * wa0 + acc[nt][3] * wa1;
        sd[hsel][0] += acc[nt][0] * wd0 + acc[nt][1] * wd1;
        sd[hsel][1] += acc[nt][2] * wd0 + acc[nt][3] * wd1;
    }
#pragma unroll
    for (int o = 1; o <= 2; o <<= 1) {
#pragma unroll
        for (int hs = 0; hs < 2; hs++)
#pragma unroll
            for (int rr = 0; rr < 2; rr++) {
                sa[hs][rr] += __shfl_xor_sync(0xffffffffu, sa[hs][rr], o);
                sd[hs][rr] += __shfl_xor_sync(0xffffffffu, sd[hs][rr], o);
            }
    }
    if (tg == 0) {
        as_[r0 * 4 + wn * 2 + 0] = sa[0][0];
        as_[r1 * 4 + wn * 2 + 0] = sa[0][1];
        as_[r0 * 4 + wn * 2 + 1] = sa[1][0];
        as_[r1 * 4 + wn * 2 + 1] = sa[1][1];
        ad_[r0 * 4 + wn * 2 + 0] = sd[0][0];
        ad_[r1 * 4 + wn * 2 + 0] = sd[0][1];
        ad_[r0 * 4 + wn * 2 + 1] = sd[1][0];
        ad_[r1 * 4 + wn * 2 + 1] = sd[1][1];
    }
}

// ---------------- GEMM2 3xTF32 mma + fused BN stats ---------------------------
__global__ __launch_bounds__(256) void k_gemm_z_mma(
    const float* __restrict__ att, const float* __restrict__ bias,
    const float* __restrict__ W, float* __restrict__ z, float* __restrict__ stats)
{
    __shared__ float As[64 * 68];
    __shared__ float Ws[64 * 72];
    __shared__ float ssum[64], ssq[64];
    int t = threadIdx.x;
    int row0 = blockIdx.x * 64;
    if (t < 64) { ssum[t] = 0.f; ssq[t] = 0.f; }

    int wid = t >> 5, lane = t & 31;
    int wm = wid & 3, wn = wid >> 2;
    int g = lane >> 2, tg = lane & 3;

    float acc[4][4];
#pragma unroll
    for (int nt = 0; nt < 4; nt++)
#pragma unroll
        for (int c = 0; c < 4; c++) acc[nt][c] = 0.f;

    const float4* att4 = (const float4*)att;
    const float4* bias4 = (const float4*)bias;
    const float4* W4 = (const float4*)W;

    for (int kc = 0; kc < 4; kc++) {
        __syncthreads();
        for (int i = t; i < 64 * 16; i += 256) {
            int r = i >> 4, c4 = i & 15;
            float4 v = att4[(size_t)(row0 + r) * 64 + kc * 16 + c4];
            float4 b = bias4[kc * 16 + c4];
            float* dp = &As[r * 68 + c4 * 4];
            dp[0] = eluf(v.x + b.x); dp[1] = eluf(v.y + b.y);
            dp[2] = eluf(v.z + b.z); dp[3] = eluf(v.w + b.w);
        }
        for (int i = t; i < 64 * 16; i += 256) {
            int r = i >> 4, c4 = i & 15;
            float4 v = W4[(size_t)(kc * 64 + r) * 16 + c4];
            float* dp = &Ws[r * 72 + c4 * 4];
            dp[0] = v.x; dp[1] = v.y; dp[2] = v.z; dp[3] = v.w;
        }
        __syncthreads();
#pragma unroll
        for (int k8 = 0; k8 < 8; k8++) {
            int kb = k8 * 8;
            float v0 = As[(wm * 16 + g) * 68 + kb + tg];
            float v1 = As[(wm * 16 + g + 8) * 68 + kb + tg];
            float v2 = As[(wm * 16 + g) * 68 + kb + tg + 4];
            float v3 = As[(wm * 16 + g + 8) * 68 + kb + tg + 4];
            float ah0 = tf32r(v0), ah1 = tf32r(v1), ah2 = tf32r(v2), ah3 = tf32r(v3);
            float al0 = tf32r(v0 - ah0), al1 = tf32r(v1 - ah1);
            float al2 = tf32r(v2 - ah2), al3 = tf32r(v3 - ah3);
#pragma unroll
            for (int nt = 0; nt < 4; nt++) {
                int n0 = wn * 32 + nt * 8;
                float w0 = Ws[(kb + tg) * 72 + n0 + g];
                float w1 = Ws[(kb + tg + 4) * 72 + n0 + g];
                float bh0 = tf32r(w0), bh1 = tf32r(w1);
                float bl0 = tf32r(w0 - bh0), bl1 = tf32r(w1 - bh1);
                mma8(acc[nt], al0, al1, al2, al3, bh0, bh1);
                mma8(acc[nt], ah0, ah1, ah2, ah3, bl0, bl1);
                mma8(acc[nt], ah0, ah1, ah2, ah3, bh0, bh1);
            }
        }
    }

    int r0 = row0 + wm * 16 + g;
    int r1 = r0 + 8;
#pragma unroll
    for (int nt = 0; nt < 4; nt++) {
        int c = wn * 32 + nt * 8 + tg * 2;
        *(float2*)&z[(size_t)r0 * 64 + c] = make_float2(acc[nt][0], acc[nt][1]);
        *(float2*)&z[(size_t)r1 * 64 + c] = make_float2(acc[nt][2], acc[nt][3]);
        atomicAdd(&ssum[c],     acc[nt][0] + acc[nt][2]);
        atomicAdd(&ssum[c + 1], acc[nt][1] + acc[nt][3]);
        atomicAdd(&ssq[c],      acc[nt][0] * acc[nt][0] + acc[nt][2] * acc[nt][2]);
        atomicAdd(&ssq[c + 1],  acc[nt][1] * acc[nt][1] + acc[nt][3] * acc[nt][3]);
    }
    __syncthreads();
    if (t < 64) {
        atomicAdd(&stats[t], ssum[t]);
        atomicAdd(&stats[FF + t], ssq[t]);
    }
}

// ---------------- per-node softmax over CSR (warp/node) -----------------------
__global__ __launch_bounds__(256) void k_softmax(
    const int* __restrict__ rowptr, const int* __restrict__ deg, const int* __restrict__ csr,
    const float* __restrict__ as_, const float* __restrict__ ad_,
    float* __restrict__ aex, float* __restrict__ sexp, float* __restrict__ inv)
{
    int n = blockIdx.x * 8 + (threadIdx.x >> 5);
    int lane = threadIdx.x & 31;
    int b = rowptr[n], dg = deg[n];
    float4 adn = ((const float4*)ad_)[n];
    float4 asn = ((const float4*)as_)[n];
    float4 self;
    self.x = lrelu(asn.x + adn.x); self.y = lrelu(asn.y + adn.y);
    self.z = lrelu(asn.z + adn.z); self.w = lrelu(asn.w + adn.w);

    float4 mx = self;
    for (int j = lane; j < dg; j += 32) {
        float4 sv = ((const float4*)as_)[csr[b + j]];
        mx.x = fmaxf(mx.x, lrelu(sv.x + adn.x));
        mx.y = fmaxf(mx.y, lrelu(sv.y + adn.y));
        mx.z = fmaxf(mx.z, lrelu(sv.z + adn.z));
        mx.w = fmaxf(mx.w, lrelu(sv.w + adn.w));
    }
#pragma unroll
    for (int o = 16; o; o >>= 1) {
        mx.x = fmaxf(mx.x, __shfl_xor_sync(0xffffffffu, mx.x, o));
        mx.y = fmaxf(mx.y, __shfl_xor_sync(0xffffffffu, mx.y, o));
        mx.z = fmaxf(mx.z, __shfl_xor_sync(0xffffffffu, mx.z, o));
        mx.w = fmaxf(mx.w, __shfl_xor_sync(0xffffffffu, mx.w, o));
    }

    float4 sum = make_float4(0.f, 0.f, 0.f, 0.f);
    for (int j = lane; j < dg; j += 32) {
        float4 sv = ((const float4*)as_)[csr[b + j]];
        float4 ex;
        ex.x = __expf(lrelu(sv.x + adn.x) - mx.x);
        ex.y = __expf(lrelu(sv.y + adn.y) - mx.y);
        ex.z = __expf(lrelu(sv.z + adn.z) - mx.z);
        ex.w = __expf(lrelu(sv.w + adn.w) - mx.w);
        ((float4*)aex)[b + j] = ex;
        sum.x += ex.x; sum.y += ex.y; sum.z += ex.z; sum.w += ex.w;
    }
#pragma unroll
    for (int o = 16; o; o >>= 1) {
        sum.x += __shfl_xor_sync(0xffffffffu, sum.x, o);
        sum.y += __shfl_xor_sync(0xffffffffu, sum.y, o);
        sum.z += __shfl_xor_sync(0xffffffffu, sum.z, o);
        sum.w += __shfl_xor_sync(0xffffffffu, sum.w, o);
    }
    if (lane == 0) {
        float4 sex;
        sex.x = __expf(self.x - mx.x); sex.y = __expf(self.y - mx.y);
        sex.z = __expf(self.z - mx.z); sex.w = __expf(self.w - mx.w);
        float4 iv;
        iv.x = 1.f / (sum.x + sex.x); iv.y = 1.f / (sum.y + sex.y);
        iv.z = 1.f / (sum.z + sex.z); iv.w = 1.f / (sum.w + sex.w);
        ((float4*)sexp)[n] = sex;
        ((float4*)inv)[n] = iv;
    }
}

// ---------------- CSR gather aggregation --------------------------------------
__global__ __launch_bounds__(256) void k_aggr(
    const int* __restrict__ rowptr, const int* __restrict__ deg, const int* __restrict__ csr,
    const float* __restrict__ aex, const float* __restrict__ sexp, const float* __restrict__ inv,
    const float* __restrict__ h, float* __restrict__ att)
{
    int t = blockIdx.x * 256 + threadIdx.x;
    int n = t >> 6, gq = t & 63, hd = gq >> 4;
    int b = rowptr[n], dg = deg[n];
    float sex = sexp[n * 4 + hd];
    float iv  = inv[n * 4 + hd];
    const float4* h4 = (const float4*)h;
    float4 acc = h4[(size_t)n * 64 + gq];
    acc.x *= sex; acc.y *= sex; acc.z *= sex; acc.w *= sex;
    for (int p = b; p < b + dg; p++) {
        int s = csr[p];
        float al = aex[p * 4 + hd];
        float4 hv = h4[(size_t)s * 64 + gq];
        acc.x += al * hv.x; acc.y += al * hv.y;
        acc.z += al * hv.z; acc.w += al * hv.w;
    }
    acc.x *= iv; acc.y *= iv; acc.z *= iv; acc.w *= iv;
    ((float4*)att)[(size_t)n * 64 + gq] = acc;
}

// ---------------- fused BN tail: pool += x + sum_br BN(z_br) ------------------
__global__ __launch_bounds__(256) void k_bnfinal(
    const float* __restrict__ Z, const float* __restrict__ stats,
    const float* __restrict__ mlpg, const float* __restrict__ mlpbe,
    const float* __restrict__ x, const int* __restrict__ batch,
    float* __restrict__ pool)
{
    __shared__ float smu[256], srs[256], sbb[256];
    int t = threadIdx.x;
    if (t < 256) {
        int br = t >> 6, f = t & 63;
        float mu = stats[br * 128 + f] * (1.f / NN);
        float var = stats[br * 128 + 64 + f] * (1.f / NN) - mu * mu;
        smu[t] = mu;
        srs[t] = rsqrtf(var + BNEPS) * mlpg[br * 64 + f];
        sbb[t] = mlpbe[br * 64 + f];
    }
    __syncthreads();
    int gidx = blockIdx.x * 256 + t;
    int n = gidx >> 4, q = gidx & 15, f0 = q * 4;
    float4 v = ((const float4*)x)[gidx];
#pragma unroll
    for (int br = 0; br < 4; br++) {
        float4 zv = ((const float4*)Z)[(size_t)br * NN * 16 + gidx];
        int o = br * 64 + f0;
        v.x += (zv.x - smu[o + 0]) * srs[o + 0] + sbb[o + 0];
        v.y += (zv.y - smu[o + 1]) * srs[o + 1] + sbb[o + 1];
        v.z += (zv.z - smu[o + 2]) * srs[o + 2] + sbb[o + 2];
        v.w += (zv.w - smu[o + 3]) * srs[o + 3] + sbb[o + 3];
    }
    red4(pool + batch[n] * 64 + f0, v);
}

// ---------------- fused FC head (single block, 1024 threads) ------------------
__global__ __launch_bounds__(1024) void k_head(
    const float* __restrict__ pool,
    const float* __restrict__ fc1W, const float* __restrict__ fc1b,
    const float* __restrict__ fc1g, const float* __restrict__ fc1be,
    const float* __restrict__ fc2W, const float* __restrict__ fc2b,
    const float* __restrict__ fc2g, const float* __restrict__ fc2be,
    const float* __restrict__ fc3W, const float* __restrict__ fc3b,
    const float* __restrict__ fc3g, const float* __restrict__ fc3be,
    float* __restrict__ out)
{
    extern __shared__ float sm[];
    float* sp = sm;
    float* y1 = sp + 64 * 65;
    float* y2 = y1 + 64 * 257;
    int t = threadIdx.x;

    for (int i = t; i < 64 * 16; i += 1024) {
        int r = i >> 4, c4 = i & 15;
        float4 v = ((const float4*)pool)[i];
        float* dp = &sp[r * 65 + c4 * 4];
        dp[0] = v.x; dp[1] = v.y; dp[2] = v.z; dp[3] = v.w;
    }
    __syncthreads();

    {
        int c = t & 255, rg = t >> 8;
        float accv[16];
        float bb = fc1b[c];
#pragma unroll
        for (int r = 0; r < 16; r++) accv[r] = bb;
        for (int k = 0; k < 64; k++) {
            float w = fc1W[k * 256 + c];
#pragma unroll
            for (int r = 0; r < 16; r++)
                accv[r] += sp[(rg * 16 + r) * 65 + k] * w;
        }
#pragma unroll
        for (int r = 0; r < 16; r++) y1[(rg * 16 + r) * 257 + c] = accv[r];
    }
    __syncthreads();
    if (t < 256) {
        float s = 0.f, ss = 0.f;
#pragma unroll 8
        for (int r = 0; r < 64; r++) { float v = y1[r * 257 + t]; s += v; ss += v * v; }
        float mu = s * (1.f / GG);
        float var = ss * (1.f / GG) - mu * mu;
        sp[t] = mu;
        sp[256 + t] = rsqrtf(var + BNEPS) * fc1g[t];
    }
    __syncthreads();
    for (int i = t; i < 64 * 256; i += 1024) {
        int r = i >> 8, c = i & 255;
        float v = (y1[r * 257 + c] - sp[c]) * sp[256 + c] + fc1be[c];
        y1[r * 257 + c] = fmaxf(v, 0.f);
    }
    __syncthreads();

    {
        int c = t & 127, rg = t >> 7;
        float accv[8];
        float bb = fc2b[c];
#pragma unroll
        for (int r = 0; r < 8; r++) accv[r] = bb;
        for (int k = 0; k < 256; k++) {
            float w = fc2W[k * 128 + c];
#pragma unroll
            for (int r = 0; r < 8; r++)
                accv[r] += y1[(rg * 8 + r) * 257 + k] * w;
        }
#pragma unroll
        for (int r = 0; r < 8; r++) y2[(rg * 8 + r) * 129 + c] = accv[r];
    }
    __syncthreads();
    if (t < 128) {
        float s = 0.f, ss = 0.f;
#pragma unroll 8
        for (int r = 0; r < 64; r++) { float v = y2[r * 129 + t]; s += v; ss += v * v; }
        float mu = s * (1.f / GG);
        float var = ss * (1.f / GG) - mu * mu;
        sp[t] = mu;
        sp[256 + t] = rsqrtf(var + BNEPS) * fc2g[t];
    }
    __syncthreads();
    for (int i = t; i < 64 * 128; i += 1024) {
        int r = i >> 7, c = i & 127;
        float v = (y2[r * 129 + c] - sp[c]) * sp[256 + c] + fc2be[c];
        y2[r * 129 + c] = fmaxf(v, 0.f);
    }
    __syncthreads();

    float* y3 = sp + 1024;
    if (t < 640) {
        int r = t / NCC, c = t % NCC;
        float acc = fc3b[c];
        for (int k = 0; k < 128; k++)
            acc += y2[r * 129 + k] * fc3W[k * NCC + c];
        y3[r * NCC + c] = acc;
    }
    __syncthreads();
    if (t < NCC) {
        float s = 0.f, ss = 0.f;
#pragma unroll 8
        for (int r = 0; r < 64; r++) { float v = y3[r * NCC + t]; s += v; ss += v * v; }
        float mu = s * (1.f / GG);
        float var = ss * (1.f / GG) - mu * mu;
        sp[t] = mu;
        sp[64 + t] = rsqrtf(var + BNEPS) * fc3g[t];
    }
    __syncthreads();
    if (t < 640) {
        int r = t / NCC, c = t % NCC;
        out[t] = (y3[r * NCC + c] - sp[c]) * sp[64 + c] + fc3be[c];
    }
}

// ---------------- host orchestration ------------------------------------------
extern "C" void kernel_launch(void* const* d_in, const int* in_sizes, int n_in,
                              void* d_out, int out_size)
{
    const float* x      = (const float*)d_in[0];
    const int*   eidx   = (const int*)d_in[1];
    const int*   batch  = (const int*)d_in[2];
    const int*   sidx   = (const int*)d_in[3];
    const float* sattr  = (const float*)d_in[4];
    const float* gatW   = (const float*)d_in[5];
    const float* gasrc  = (const float*)d_in[6];
    const float* gadst  = (const float*)d_in[7];
    const float* gatb   = (const float*)d_in[8];
    const float* mlpW   = (const float*)d_in[9];
    const float* mlpg   = (const float*)d_in[11];
    const float* mlpbe  = (const float*)d_in[12];
    const float* fc1W   = (const float*)d_in[13];
    const float* fc1b   = (const float*)d_in[14];
    const float* fc1g   = (const float*)d_in[15];
    const float* fc1be  = (const float*)d_in[16];
    const float* fc2W   = (const float*)d_in[17];
    const float* fc2b   = (const float*)d_in[18];
    const float* fc2g   = (const float*)d_in[19];
    const float* fc2be  = (const float*)d_in[20];
    const float* fc3W   = (const float*)d_in[21];
    const float* fc3b   = (const float*)d_in[22];
    const float* fc3g   = (const float*)d_in[23];
    const float* fc3be  = (const float*)d_in[24];
    float* out = (float*)d_out;

    float* A;
    cudaGetSymbolAddress((void**)&A, g_arena);
    int* IA;
    cudaGetSymbolAddress((void**)&IA, g_iarena);

    float* B0   = A + O_B0;
    float* BR   = A + O_BR;
    float* X123 = A + O_X;
    float* H    = A + O_H;
    float* ATT  = A + O_ATT;
    float* AS   = A + O_AS;
    float* AD   = A + O_AD;
    float* AEX  = A + O_AEX;
    float* SEXP = A + O_SEXP;
    float* INV  = A + O_INV;
    float* CA   = A + O_CA;
    float* Z    = A + O_Z;
    float* ST   = A + O_STATS;
    float* POOL = A + O_POOL;

    int* DEG  = IA + I_DEG;
    int* CUR  = IA + I_CUR;
    int* RP   = IA + I_RP;
    int* CSRE = IA + I_CSRE;
    int* CSR0 = IA + I_CSR0;
    int* BSUM = IA + I_BSUM;

    static int configured = 0;
    if (!configured) {
        cudaFuncSetAttribute(k_head, cudaFuncAttributeMaxDynamicSharedMemorySize, 120 * 1024);
        cudaFuncSetAttribute(k_gemm_h_mma, cudaFuncAttributeMaxDynamicSharedMemorySize, 90 * 1024);
        configured = 1;
    }

    // ---- CSR builds (all 5 sets merged) ----
    cudaMemsetAsync(DEG, 0, 5 * NN * sizeof(int));
    cudaMemsetAsync(ST, 0, 512 * sizeof(float));
    cudaMemsetAsync(POOL, 0, (size_t)GG * FF * sizeof(float));
    dim3 h5(EGZ / 256, 5);
    k_hist5<<<h5, 256>>>(eidx, sidx, DEG);
    dim3 b5(NN / 256, 5);
    k_blocksum5<<<b5, 256>>>(DEG, BSUM);
    k_scanbs5<<<5, 128>>>(BSUM);
    k_scanout5<<<b5, 256>>>(DEG, BSUM, RP, CUR);
    k_fillE<<<EGZ / 256, 256>>>(eidx, CUR, CSRE);
    dim3 f4(ESZ / 256, 4);
    k_fillS<<<f4, 256>>>(sidx, sattr, CUR, CSR0, CA);

    // ---- gather stage (all CSR-based now) ----
    dim3 gbr(NN * 16 / 256, 3);
    k_gatherBR<<<gbr, 256>>>(RP, DEG, CSR0, CA, x, BR);
    dim3 gg(NN * 16 / 256, 4);
    k_gather4<<<gg, 256>>>(RP, DEG, CSR0, CA, x, BR, B0, X123);

    const float* bx[4] = { B0, X123, X123 + NN * FF, X123 + 2 * NN * FF };

    const int smem1 = (64 * 68 + 64 * 264) * sizeof(float);

    // ---- 4 GAT branches ----
    for (int br = 0; br < 4; br++) {
        k_gemm_h_mma<<<NN / 64, 256, smem1>>>(bx[br], gatW + br * FF * HFD,
                                              gasrc + br * HH * FF, gadst + br * HH * FF,
                                              H, AS, AD);
        k_softmax<<<NN / 8, 256>>>(RP, DEG, CSRE, AS, AD, AEX, SEXP, INV);
        k_aggr<<<NN * 64 / 256, 256>>>(RP, DEG, CSRE, AEX, SEXP, INV, H, ATT);
        k_gemm_z_mma<<<NN / 64, 256>>>(ATT, gatb + br * HFD, mlpW + br * HFD * FF,
                                       Z + (size_t)br * NN * FF, ST + br * 128);
    }

    // ---- fused BN tail + pool ----
    k_bnfinal<<<NN * 16 / 256, 256>>>(Z, ST, mlpg, mlpbe, x, batch, POOL);

    // ---- fused head ----
    k_head<<<1, 1024, (64 * 65 + 64 * 257 + 64 * 129) * sizeof(float)>>>(
        POOL, fc1W, fc1b, fc1g, fc1be, fc2W, fc2b, fc2g, fc2be,
        fc3W, fc3b, fc3g, fc3be, out);
}